// round 6
// baseline (speedup 1.0000x reference)
#include <cuda_runtime.h>
#include <cuda_fp16.h>

#define NN 100000
#define NE 3200000
#define DIMK 256
#define NC 32
#define NG 64
#define BR 256                 // rows per block in gemm
#define NBLK ((NN + 1023) / 1024)   // scan blocks = 98

// Scratch (device globals; no allocation allowed)
__device__ int    g_cnt_i[NN];              // in-degree (no self loop)
__device__ int    g_off[NN];                // CSR start offsets
__device__ int    g_cur[NN];                // build cursors
__device__ int    g_blk[NBLK];              // scan block sums
__device__ int    g_esrc[NE];               // CSR: src node per edge, bucketed by dst
__device__ float  g_dinv[NN];
__device__ __half g_hs_h[(size_t)NN * NC];  // h * dinv[row] in fp16 (gather payload)
__device__ float  g_agg[(size_t)NN * NC];   // sum of hs over in-edges (+ self hs)
__device__ float  g_pool[NG * NC];
__device__ float  g_cnt[NG];

// f32x2 packed helpers (Blackwell packed fp32)
__device__ __forceinline__ unsigned long long pk2(float a, float b) {
    unsigned long long r;
    asm("mov.b64 %0, {%1, %2};" : "=l"(r) : "f"(a), "f"(b));
    return r;
}
__device__ __forceinline__ void ffma2(unsigned long long& d, unsigned long long a,
                                      unsigned long long b) {
    asm("fma.rn.f32x2 %0, %1, %2, %0;" : "+l"(d) : "l"(a), "l"(b));
}
__device__ __forceinline__ void upk2(unsigned long long v, float& lo, float& hi) {
    asm("mov.b64 {%0, %1}, %2;" : "=f"(lo), "=f"(hi) : "l"(v));
}

// ---------------------------------------------------------------- init
__global__ void k_init() {
    int i = blockIdx.x * blockDim.x + threadIdx.x;
    if (i < NN) g_cnt_i[i] = 0;
    if (i < NG * NC) g_pool[i] = 0.0f;
    if (i < NG) g_cnt[i] = 0.0f;
}

// ---------------------------------------------------------------- degree (int)
__global__ void k_cnt(const int* __restrict__ dst) {
    int i = blockIdx.x * blockDim.x + threadIdx.x;
    if (i * 4 < NE) {
        int4 d = ((const int4*)dst)[i];
        atomicAdd(&g_cnt_i[d.x], 1);
        atomicAdd(&g_cnt_i[d.y], 1);
        atomicAdd(&g_cnt_i[d.z], 1);
        atomicAdd(&g_cnt_i[d.w], 1);
    }
}

// ---------------------------------------------------------------- exclusive scan
__global__ void k_scanA() {
    __shared__ int wt[8];
    int tid = threadIdx.x, lane = tid & 31, w = tid >> 5;
    int base = blockIdx.x * 1024 + tid * 4;
    int v[4];
#pragma unroll
    for (int k = 0; k < 4; k++) {
        int i = base + k;
        v[k] = (i < NN) ? g_cnt_i[i] : 0;
    }
    int t = v[0] + v[1] + v[2] + v[3];
    int s = t;
#pragma unroll
    for (int o = 1; o < 32; o <<= 1) {
        int u = __shfl_up_sync(0xffffffffu, s, o);
        if (lane >= o) s += u;
    }
    if (lane == 31) wt[w] = s;
    __syncthreads();
    if (tid == 0) {
        int r = 0;
#pragma unroll
        for (int i = 0; i < 8; i++) { int u = wt[i]; wt[i] = r; r += u; }
        g_blk[blockIdx.x] = r;   // block total
    }
    __syncthreads();
    int run = wt[w] + s - t;     // exclusive base for this thread
#pragma unroll
    for (int k = 0; k < 4; k++) {
        int i = base + k;
        if (i < NN) g_off[i] = run;
        run += v[k];
    }
}

__global__ void k_scanB() {
    __shared__ int sm[128];
    int tid = threadIdx.x;
    int mine = (tid < NBLK) ? g_blk[tid] : 0;
    sm[tid] = mine;
    __syncthreads();
    for (int o = 1; o < 128; o <<= 1) {
        int u = (tid >= o) ? sm[tid - o] : 0;
        __syncthreads();
        sm[tid] += u;
        __syncthreads();
    }
    if (tid < NBLK) g_blk[tid] = sm[tid] - mine;   // exclusive
}

__global__ void k_scanC() {
    int i = blockIdx.x * blockDim.x + threadIdx.x;
    if (i < NN) {
        int o = g_off[i] + g_blk[i >> 10];
        g_off[i] = o;
        g_cur[i] = o;
    }
}

// ---------------------------------------------------------------- dinv
__global__ void k_dinv() {
    int i = blockIdx.x * blockDim.x + threadIdx.x;
    if (i < NN) g_dinv[i] = rsqrtf((float)g_cnt_i[i] + 1.0f);  // +1 self loop
}

// ---------------------------------------------------------------- CSR build
__global__ void k_build(const int* __restrict__ src, const int* __restrict__ dst) {
    int i = blockIdx.x * blockDim.x + threadIdx.x;
    if (i * 4 < NE) {
        int4 s = ((const int4*)src)[i];
        int4 d = ((const int4*)dst)[i];
        int p;
        p = atomicAdd(&g_cur[d.x], 1); g_esrc[p] = s.x;
        p = atomicAdd(&g_cur[d.y], 1); g_esrc[p] = s.y;
        p = atomicAdd(&g_cur[d.z], 1); g_esrc[p] = s.z;
        p = atomicAdd(&g_cur[d.w], 1); g_esrc[p] = s.w;
    }
}

// ---------------------------------------------------------------- GEMM + self term
// Register-tiled: thread = 8 rows x 4 cols, row-paired f32x2 accumulators.
__global__ void __launch_bounds__(256, 2) k_gemm(const float* __restrict__ x,
                                                 const float* __restrict__ W) {
    __shared__ float Ws[DIMK][NC];   // 32KB

    int tid = threadIdx.x, warp = tid >> 5, lane = tid & 31;

    for (int i = tid; i < DIMK * NC / 4; i += 256)
        ((float4*)Ws)[i] = ((const float4*)W)[i];
    __syncthreads();

    int cg = lane & 7;    // col group: cols 4cg..4cg+3
    int rg = lane >> 3;   // row group: 8 rows
    int row0 = blockIdx.x * BR + warp * 32 + rg * 8;

    const float4* xr[8];
#pragma unroll
    for (int r = 0; r < 8; r++) {
        int rr = row0 + r; if (rr >= NN) rr = NN - 1;
        xr[r] = (const float4*)(x + (size_t)rr * DIMK);
    }

    unsigned long long acc[4][4];
#pragma unroll
    for (int rp = 0; rp < 4; rp++)
#pragma unroll
        for (int c = 0; c < 4; c++) acc[rp][c] = 0ull;

#pragma unroll 4
    for (int kq = 0; kq < DIMK / 4; kq++) {
        float4 xv[8];
#pragma unroll
        for (int r = 0; r < 8; r++) xv[r] = xr[r][kq];   // dedup'd LDG.128

#pragma unroll
        for (int kk = 0; kk < 4; kk++) {
            float4 wv = *(const float4*)&Ws[4 * kq + kk][4 * cg];  // broadcast LDS
            unsigned long long wd[4];
            wd[0] = pk2(wv.x, wv.x); wd[1] = pk2(wv.y, wv.y);
            wd[2] = pk2(wv.z, wv.z); wd[3] = pk2(wv.w, wv.w);
#pragma unroll
            for (int rp = 0; rp < 4; rp++) {
                float a = (kk == 0) ? xv[2*rp].x : (kk == 1) ? xv[2*rp].y
                         : (kk == 2) ? xv[2*rp].z : xv[2*rp].w;
                float bq = (kk == 0) ? xv[2*rp+1].x : (kk == 1) ? xv[2*rp+1].y
                         : (kk == 2) ? xv[2*rp+1].z : xv[2*rp+1].w;
                unsigned long long xp = pk2(a, bq);
#pragma unroll
                for (int c = 0; c < 4; c++) ffma2(acc[rp][c], xp, wd[c]);
            }
        }
    }

#pragma unroll
    for (int rp = 0; rp < 4; rp++) {
        float h0[4], h1[4];
#pragma unroll
        for (int c = 0; c < 4; c++) upk2(acc[rp][c], h0[c], h1[c]);
#pragma unroll
        for (int half_ = 0; half_ < 2; half_++) {
            int row = row0 + 2 * rp + half_;
            if (row < NN) {
                float* hv = half_ ? h1 : h0;
                float di = g_dinv[row];
                float4 hs4 = make_float4(hv[0]*di, hv[1]*di, hv[2]*di, hv[3]*di);
                *(float4*)&g_agg[(size_t)row * NC + 4 * cg] = hs4;   // self-loop seed
                half2 p0 = __floats2half2_rn(hs4.x, hs4.y);
                half2 p1 = __floats2half2_rn(hs4.z, hs4.w);
                *(uint2*)&g_hs_h[(size_t)row * NC + 4 * cg] =
                    make_uint2(*(unsigned*)&p0, *(unsigned*)&p1);
            }
        }
    }
}

// ---------------------------------------------------------------- gather
// Warp per dst node. 8 lanes/edge, 4 edges in flight. No atomics: register
// accumulate -> shuffle combine -> single float4 RMW of the gemm seed.
__global__ void __launch_bounds__(256) k_gather() {
    int gw = (blockIdx.x * blockDim.x + threadIdx.x) >> 5;
    if (gw >= NN) return;
    int lane = threadIdx.x & 31;
    int g  = lane >> 3;   // edge subgroup 0..3
    int l8 = lane & 7;    // channel quad

    int start = g_off[gw];
    int cnt   = g_cnt_i[gw];

    const uint2* hs2 = (const uint2*)g_hs_h;
    float a0 = 0.0f, a1 = 0.0f, a2 = 0.0f, a3 = 0.0f;

#pragma unroll 2
    for (int j = g; j < cnt; j += 4) {
        int es = g_esrc[start + j];           // uniform across 8 lanes (dedup'd)
        uint2 hv = hs2[(size_t)es * 8 + l8];
        float2 fa = __half22float2(*(half2*)&hv.x);
        float2 fb = __half22float2(*(half2*)&hv.y);
        a0 += fa.x; a1 += fa.y; a2 += fb.x; a3 += fb.y;
    }
    // combine subgroups 1,2,3 into 0 (distance 16 then 8)
    a0 += __shfl_down_sync(0xffffffffu, a0, 16);
    a1 += __shfl_down_sync(0xffffffffu, a1, 16);
    a2 += __shfl_down_sync(0xffffffffu, a2, 16);
    a3 += __shfl_down_sync(0xffffffffu, a3, 16);
    a0 += __shfl_down_sync(0xffffffffu, a0, 8);
    a1 += __shfl_down_sync(0xffffffffu, a1, 8);
    a2 += __shfl_down_sync(0xffffffffu, a2, 8);
    a3 += __shfl_down_sync(0xffffffffu, a3, 8);

    if (lane < 8) {
        float4* p = (float4*)&g_agg[(size_t)gw * NC + l8 * 4];
        float4 seed = *p;                      // gemm self-loop term
        *p = make_float4(seed.x + a0, seed.y + a1, seed.z + a2, seed.w + a3);
    }
}

// ---------------------------------------------------------------- pooling
__global__ void __launch_bounds__(256) k_pool(const int* __restrict__ batch) {
    __shared__ float sp[NG * NC];
    __shared__ float sc[NG];
    int tid = threadIdx.x;
    for (int i = tid; i < NG * NC; i += 256) sp[i] = 0.0f;
    if (tid < NG) sc[tid] = 0.0f;
    __syncthreads();

    int warp = tid >> 5, lane = tid & 31;
    int wid = blockIdx.x * 8 + warp;
    int nwarps = gridDim.x * 8;
    int per = (NN + nwarps - 1) / nwarps;
    int s0 = wid * per;
    int s1 = min(NN, s0 + per);

    float acc = 0.0f, cacc = 0.0f;
    int curg = -1;
    for (int i = s0; i < s1; i++) {
        int gidx = __ldg(&batch[i]);
        if (gidx != curg) {
            if (curg >= 0) {
                atomicAdd(&sp[curg * NC + lane], acc);
                if (lane == 0) atomicAdd(&sc[curg], cacc);
            }
            curg = gidx; acc = 0.0f; cacc = 0.0f;
        }
        float di = g_dinv[i];
        acc  += g_agg[(size_t)i * NC + lane] * di;
        cacc += 1.0f;
    }
    if (curg >= 0) {
        atomicAdd(&sp[curg * NC + lane], acc);
        if (lane == 0) atomicAdd(&sc[curg], cacc);
    }
    __syncthreads();

    for (int i = tid; i < NG * NC; i += 256) atomicAdd(&g_pool[i], sp[i]);
    if (tid < NG) atomicAdd(&g_cnt[tid], sc[tid]);
}

// ---------------------------------------------------------------- finalize
__global__ void k_final(const float* __restrict__ b, float* __restrict__ out) {
    int i = blockIdx.x * blockDim.x + threadIdx.x;
    if (i < NG * NC) {
        int g = i >> 5, c = i & 31;
        float cnt = g_cnt[g];
        out[i] = (cnt > 0.0f) ? (g_pool[i] / cnt + b[c]) : 0.0f;
    }
}

// ---------------------------------------------------------------- launch
extern "C" void kernel_launch(void* const* d_in, const int* in_sizes, int n_in,
                              void* d_out, int out_size) {
    const float* x     = (const float*)d_in[0];
    const float* W     = (const float*)d_in[1];
    const float* b     = (const float*)d_in[2];
    const int*   ei    = (const int*)d_in[3];
    const int*   batch = (const int*)d_in[4];
    float*       out   = (float*)d_out;

    const int* src = ei;        // edge_index[0]
    const int* dst = ei + NE;   // edge_index[1]

    k_init <<<(NN + 255) / 256, 256>>>();
    k_cnt  <<<(NE / 4 + 255) / 256, 256>>>(dst);
    k_scanA<<<NBLK, 256>>>();
    k_scanB<<<1, 128>>>();
    k_scanC<<<(NN + 255) / 256, 256>>>();
    k_dinv <<<(NN + 255) / 256, 256>>>();
    k_build<<<(NE / 4 + 255) / 256, 256>>>(src, dst);
    k_gemm <<<(NN + BR - 1) / BR, 256>>>(x, W);
    k_gather<<<(NN + 7) / 8, 256>>>();
    k_pool <<<64, 256>>>(batch);
    k_final<<<(NG * NC + 255) / 256, 256>>>(b, out);
}

// round 7
// speedup vs baseline: 1.1103x; 1.1103x over previous
#include <cuda_runtime.h>
#include <cuda_fp16.h>

#define NN 100000
#define NE 3200000
#define DIMK 256
#define NC 32
#define NG 64
#define BR 256     // rows per block in gemm
#define CAP 96     // fixed CSR stride (deg ~ Poisson(32); P(>=96) ~ 1e-18)
#define OVFCAP 8192

// Scratch (device globals; no allocation allowed)
__device__ int    g_cur[NN];                      // build cursor == final in-degree
__device__ int    g_esrc[(size_t)NN * CAP];       // fixed-stride CSR src lists (38.4MB)
__device__ int2   g_ovf[OVFCAP];                  // overflow edges (expected: none)
__device__ int    g_ovfn;
__device__ float  g_dinv[NN];
__device__ __half g_hs_h[(size_t)NN * NC];        // h * dinv[row] fp16 gather payload
__device__ float  g_agg[(size_t)NN * NC];         // self seed + edge sums (f32)
__device__ float  g_pool[NG * NC];
__device__ float  g_cnt[NG];

// f32x2 packed helpers (Blackwell packed fp32)
__device__ __forceinline__ unsigned long long pk2(float a, float b) {
    unsigned long long r;
    asm("mov.b64 %0, {%1, %2};" : "=l"(r) : "f"(a), "f"(b));
    return r;
}
__device__ __forceinline__ void ffma2(unsigned long long& d, unsigned long long a,
                                      unsigned long long b) {
    asm("fma.rn.f32x2 %0, %1, %2, %0;" : "+l"(d) : "l"(a), "l"(b));
}
__device__ __forceinline__ void upk2(unsigned long long v, float& lo, float& hi) {
    asm("mov.b64 {%0, %1}, %2;" : "=f"(lo), "=f"(hi) : "l"(v));
}

// ---------------------------------------------------------------- zero pads
// (split so k_build lands at launch slot 4 for ncu capture)
__global__ void k_zero1() {
    int i = blockIdx.x * blockDim.x + threadIdx.x;
    if (i < NG * NC) g_pool[i] = 0.0f;
    if (i < NG) g_cnt[i] = 0.0f;
    if (i == 0) g_ovfn = 0;
}
__global__ void k_zero2() {
    int i = blockIdx.x * blockDim.x + threadIdx.x;
    if (i < NN / 2) g_cur[i] = 0;
}
__global__ void k_zero3() {
    int i = blockIdx.x * blockDim.x + threadIdx.x;
    if (i + NN / 2 < NN) g_cur[i + NN / 2] = 0;
}

// ---------------------------------------------------------------- CSR build
// ONE atomic edge pass: cursor atomics produce degrees AND bucket placement.
__global__ void k_build(const int* __restrict__ src, const int* __restrict__ dst) {
    int i = blockIdx.x * blockDim.x + threadIdx.x;
    if (i * 4 < NE) {
        int4 s = ((const int4*)src)[i];
        int4 d = ((const int4*)dst)[i];
#pragma unroll
        for (int k = 0; k < 4; k++) {
            int dd = (k == 0) ? d.x : (k == 1) ? d.y : (k == 2) ? d.z : d.w;
            int ss = (k == 0) ? s.x : (k == 1) ? s.y : (k == 2) ? s.z : s.w;
            int p = atomicAdd(&g_cur[dd], 1);
            if (p < CAP) {
                g_esrc[(size_t)dd * CAP + p] = ss;
            } else {
                int q = atomicAdd(&g_ovfn, 1);
                if (q < OVFCAP) g_ovf[q] = make_int2(ss, dd);
            }
        }
    }
}

// ---------------------------------------------------------------- dinv
__global__ void k_dinv() {
    int i = blockIdx.x * blockDim.x + threadIdx.x;
    if (i < NN) g_dinv[i] = rsqrtf((float)g_cur[i] + 1.0f);  // +1 self loop
}

// ---------------------------------------------------------------- GEMM + self term
// Register-tiled: thread = 8 rows x 4 cols, row-paired f32x2 accumulators.
__global__ void __launch_bounds__(256, 2) k_gemm(const float* __restrict__ x,
                                                 const float* __restrict__ W) {
    __shared__ float Ws[DIMK][NC];   // 32KB

    int tid = threadIdx.x, warp = tid >> 5, lane = tid & 31;

    for (int i = tid; i < DIMK * NC / 4; i += 256)
        ((float4*)Ws)[i] = ((const float4*)W)[i];
    __syncthreads();

    int cg = lane & 7;    // col group: cols 4cg..4cg+3
    int rg = lane >> 3;   // row group: 8 rows
    int row0 = blockIdx.x * BR + warp * 32 + rg * 8;

    const float4* xr[8];
#pragma unroll
    for (int r = 0; r < 8; r++) {
        int rr = row0 + r; if (rr >= NN) rr = NN - 1;
        xr[r] = (const float4*)(x + (size_t)rr * DIMK);
    }

    unsigned long long acc[4][4];
#pragma unroll
    for (int rp = 0; rp < 4; rp++)
#pragma unroll
        for (int c = 0; c < 4; c++) acc[rp][c] = 0ull;

#pragma unroll 4
    for (int kq = 0; kq < DIMK / 4; kq++) {
        float4 xv[8];
#pragma unroll
        for (int r = 0; r < 8; r++) xv[r] = xr[r][kq];   // dedup'd LDG.128

#pragma unroll
        for (int kk = 0; kk < 4; kk++) {
            float4 wv = *(const float4*)&Ws[4 * kq + kk][4 * cg];  // broadcast LDS
            unsigned long long wd[4];
            wd[0] = pk2(wv.x, wv.x); wd[1] = pk2(wv.y, wv.y);
            wd[2] = pk2(wv.z, wv.z); wd[3] = pk2(wv.w, wv.w);
#pragma unroll
            for (int rp = 0; rp < 4; rp++) {
                float a = (kk == 0) ? xv[2*rp].x : (kk == 1) ? xv[2*rp].y
                         : (kk == 2) ? xv[2*rp].z : xv[2*rp].w;
                float bq = (kk == 0) ? xv[2*rp+1].x : (kk == 1) ? xv[2*rp+1].y
                         : (kk == 2) ? xv[2*rp+1].z : xv[2*rp+1].w;
                unsigned long long xp = pk2(a, bq);
#pragma unroll
                for (int c = 0; c < 4; c++) ffma2(acc[rp][c], xp, wd[c]);
            }
        }
    }

#pragma unroll
    for (int rp = 0; rp < 4; rp++) {
        float h0[4], h1[4];
#pragma unroll
        for (int c = 0; c < 4; c++) upk2(acc[rp][c], h0[c], h1[c]);
#pragma unroll
        for (int half_ = 0; half_ < 2; half_++) {
            int row = row0 + 2 * rp + half_;
            if (row < NN) {
                float* hv = half_ ? h1 : h0;
                float di = g_dinv[row];
                float4 hs4 = make_float4(hv[0]*di, hv[1]*di, hv[2]*di, hv[3]*di);
                *(float4*)&g_agg[(size_t)row * NC + 4 * cg] = hs4;   // self-loop seed
                half2 p0 = __floats2half2_rn(hs4.x, hs4.y);
                half2 p1 = __floats2half2_rn(hs4.z, hs4.w);
                *(uint2*)&g_hs_h[(size_t)row * NC + 4 * cg] =
                    make_uint2(*(unsigned*)&p0, *(unsigned*)&p1);
            }
        }
    }
}

// ---------------------------------------------------------------- gather
// Warp per dst node, atomic-free. 8 lanes/edge, 4 edges in flight.
__global__ void __launch_bounds__(256) k_gather() {
    int gw = (blockIdx.x * blockDim.x + threadIdx.x) >> 5;
    if (gw >= NN) return;
    int lane = threadIdx.x & 31;
    int g  = lane >> 3;   // edge subgroup 0..3
    int l8 = lane & 7;    // channel quad

    size_t start = (size_t)gw * CAP;
    int cnt = g_cur[gw];
    if (cnt > CAP) cnt = CAP;   // overflow handled by k_fix

    const uint2* hs2 = (const uint2*)g_hs_h;
    float a0 = 0.0f, a1 = 0.0f, a2 = 0.0f, a3 = 0.0f;

#pragma unroll 4
    for (int j = g; j < cnt; j += 4) {
        int es = g_esrc[start + j];           // uniform across 8 lanes (dedup'd)
        uint2 hv = hs2[(size_t)es * 8 + l8];
        float2 fa = __half22float2(*(half2*)&hv.x);
        float2 fb = __half22float2(*(half2*)&hv.y);
        a0 += fa.x; a1 += fa.y; a2 += fb.x; a3 += fb.y;
    }
    a0 += __shfl_down_sync(0xffffffffu, a0, 16);
    a1 += __shfl_down_sync(0xffffffffu, a1, 16);
    a2 += __shfl_down_sync(0xffffffffu, a2, 16);
    a3 += __shfl_down_sync(0xffffffffu, a3, 16);
    a0 += __shfl_down_sync(0xffffffffu, a0, 8);
    a1 += __shfl_down_sync(0xffffffffu, a1, 8);
    a2 += __shfl_down_sync(0xffffffffu, a2, 8);
    a3 += __shfl_down_sync(0xffffffffu, a3, 8);

    if (lane < 8) {
        float4* p = (float4*)&g_agg[(size_t)gw * NC + l8 * 4];
        float4 seed = *p;                      // gemm self-loop term
        *p = make_float4(seed.x + a0, seed.y + a1, seed.z + a2, seed.w + a3);
    }
}

// ---------------------------------------------------------------- overflow fixup
// Expected empty; exact-correctness safety net for CAP overflow.
__global__ void k_fix() {
    int n = g_ovfn;
    if (n > OVFCAP) n = OVFCAP;
    int lane = threadIdx.x & 31;
    int g  = lane >> 3;
    int l8 = lane & 7;
    const uint2* hs2 = (const uint2*)g_hs_h;
    int wid = (blockIdx.x * blockDim.x + threadIdx.x) >> 5;
    int nw  = (gridDim.x * blockDim.x) >> 5;
    for (int j = wid * 4 + g; j < n; j += nw * 4) {
        int2 e = g_ovf[j];
        uint2 hv = hs2[(size_t)e.x * 8 + l8];
        float2 fa = __half22float2(*(half2*)&hv.x);
        float2 fb = __half22float2(*(half2*)&hv.y);
        float* p = &g_agg[(size_t)e.y * NC + l8 * 4];
        asm volatile("red.global.add.v4.f32 [%0], {%1, %2, %3, %4};"
                     :: "l"(p), "f"(fa.x), "f"(fa.y), "f"(fb.x), "f"(fb.y)
                     : "memory");
    }
}

// ---------------------------------------------------------------- pooling
__global__ void __launch_bounds__(256) k_pool(const int* __restrict__ batch) {
    __shared__ float sp[NG * NC];
    __shared__ float sc[NG];
    int tid = threadIdx.x;
    for (int i = tid; i < NG * NC; i += 256) sp[i] = 0.0f;
    if (tid < NG) sc[tid] = 0.0f;
    __syncthreads();

    int warp = tid >> 5, lane = tid & 31;
    int wid = blockIdx.x * 8 + warp;
    int nwarps = gridDim.x * 8;
    int per = (NN + nwarps - 1) / nwarps;
    int s0 = wid * per;
    int s1 = min(NN, s0 + per);

    float acc = 0.0f, cacc = 0.0f;
    int curg = -1;
    for (int i = s0; i < s1; i++) {
        int gidx = __ldg(&batch[i]);
        if (gidx != curg) {
            if (curg >= 0) {
                atomicAdd(&sp[curg * NC + lane], acc);
                if (lane == 0) atomicAdd(&sc[curg], cacc);
            }
            curg = gidx; acc = 0.0f; cacc = 0.0f;
        }
        float di = g_dinv[i];
        acc  += g_agg[(size_t)i * NC + lane] * di;
        cacc += 1.0f;
    }
    if (curg >= 0) {
        atomicAdd(&sp[curg * NC + lane], acc);
        if (lane == 0) atomicAdd(&sc[curg], cacc);
    }
    __syncthreads();

    for (int i = tid; i < NG * NC; i += 256) atomicAdd(&g_pool[i], sp[i]);
    if (tid < NG) atomicAdd(&g_cnt[tid], sc[tid]);
}

// ---------------------------------------------------------------- finalize
__global__ void k_final(const float* __restrict__ b, float* __restrict__ out) {
    int i = blockIdx.x * blockDim.x + threadIdx.x;
    if (i < NG * NC) {
        int g = i >> 5, c = i & 31;
        float cnt = g_cnt[g];
        out[i] = (cnt > 0.0f) ? (g_pool[i] / cnt + b[c]) : 0.0f;
    }
}

// ---------------------------------------------------------------- launch
extern "C" void kernel_launch(void* const* d_in, const int* in_sizes, int n_in,
                              void* d_out, int out_size) {
    const float* x     = (const float*)d_in[0];
    const float* W     = (const float*)d_in[1];
    const float* b     = (const float*)d_in[2];
    const int*   ei    = (const int*)d_in[3];
    const int*   batch = (const int*)d_in[4];
    float*       out   = (float*)d_out;

    const int* src = ei;        // edge_index[0]
    const int* dst = ei + NE;   // edge_index[1]

    k_zero1<<<(NG * NC + 255) / 256, 256>>>();
    k_zero2<<<(NN / 2 + 255) / 256, 256>>>();
    k_zero3<<<(NN / 2 + 255) / 256, 256>>>();
    k_build<<<(NE / 4 + 255) / 256, 256>>>(src, dst);   // launch slot 4 -> ncu
    k_dinv <<<(NN + 255) / 256, 256>>>();
    k_gemm <<<(NN + BR - 1) / BR, 256>>>(x, W);
    k_gather<<<(NN + 7) / 8, 256>>>();
    k_fix  <<<16, 256>>>();
    k_pool <<<64, 256>>>(batch);
    k_final<<<(NG * NC + 255) / 256, 256>>>(b, out);
}

// round 8
// speedup vs baseline: 1.1154x; 1.0046x over previous
#include <cuda_runtime.h>
#include <cuda_fp16.h>

#define NN 100000
#define NE 3200000
#define DIMK 256
#define NC 32
#define NG 64
#define BR 256     // rows per block in gemm
#define CAP 96     // fixed CSR stride (deg ~ Poisson(32); P(>=96) ~ 1e-18)
#define OVFCAP 8192

// Scratch (device globals; no allocation allowed)
__device__ int    g_cur[NN];                      // build cursor == final in-degree
__device__ int    g_esrc[(size_t)NN * CAP];       // fixed-stride CSR src lists (38.4MB)
__device__ int2   g_ovf[OVFCAP];                  // overflow edges (expected: none)
__device__ int    g_ovfn;
__device__ __half g_hs_h[(size_t)NN * NC];        // h * dinv[row] fp16 gather payload
__device__ float  g_agg[(size_t)NN * NC];         // self seed + edge sums (f32)
__device__ float  g_pool[NG * NC];
__device__ float  g_cnt[NG];

// f32x2 packed helpers (Blackwell packed fp32)
__device__ __forceinline__ unsigned long long pk2(float a, float b) {
    unsigned long long r;
    asm("mov.b64 %0, {%1, %2};" : "=l"(r) : "f"(a), "f"(b));
    return r;
}
__device__ __forceinline__ void ffma2(unsigned long long& d, unsigned long long a,
                                      unsigned long long b) {
    asm("fma.rn.f32x2 %0, %1, %2, %0;" : "+l"(d) : "l"(a), "l"(b));
}
__device__ __forceinline__ void upk2(unsigned long long v, float& lo, float& hi) {
    asm("mov.b64 {%0, %1}, %2;" : "=f"(lo), "=f"(hi) : "l"(v));
}

// ---------------------------------------------------------------- zero
__global__ void k_zero() {
    int i = blockIdx.x * blockDim.x + threadIdx.x;
    if (i < NN) g_cur[i] = 0;
    if (i < NG * NC) g_pool[i] = 0.0f;
    if (i < NG) g_cnt[i] = 0.0f;
    if (i == 0) g_ovfn = 0;
}

// ---------------------------------------------------------------- CSR build
// ONE atomic edge pass: cursor atomics produce degrees AND bucket placement.
__global__ void k_build(const int* __restrict__ src, const int* __restrict__ dst) {
    int i = blockIdx.x * blockDim.x + threadIdx.x;
    if (i * 4 < NE) {
        int4 s = ((const int4*)src)[i];
        int4 d = ((const int4*)dst)[i];
#pragma unroll
        for (int k = 0; k < 4; k++) {
            int dd = (k == 0) ? d.x : (k == 1) ? d.y : (k == 2) ? d.z : d.w;
            int ss = (k == 0) ? s.x : (k == 1) ? s.y : (k == 2) ? s.z : s.w;
            int p = atomicAdd(&g_cur[dd], 1);
            if (p < CAP) {
                g_esrc[(size_t)dd * CAP + p] = ss;
            } else {
                int q = atomicAdd(&g_ovfn, 1);
                if (q < OVFCAP) g_ovf[q] = make_int2(ss, dd);
            }
        }
    }
}

// ---------------------------------------------------------------- GEMM + self term
// Register-tiled: thread = 8 rows x 4 cols, row-paired f32x2 accumulators.
// dinv computed inline from g_cur (no separate dinv kernel).
__global__ void __launch_bounds__(256, 2) k_gemm(const float* __restrict__ x,
                                                 const float* __restrict__ W) {
    __shared__ float Ws[DIMK][NC];   // 32KB

    int tid = threadIdx.x, warp = tid >> 5, lane = tid & 31;

    for (int i = tid; i < DIMK * NC / 4; i += 256)
        ((float4*)Ws)[i] = ((const float4*)W)[i];
    __syncthreads();

    int cg = lane & 7;    // col group: cols 4cg..4cg+3
    int rg = lane >> 3;   // row group: 8 rows
    int row0 = blockIdx.x * BR + warp * 32 + rg * 8;

    const float4* xr[8];
#pragma unroll
    for (int r = 0; r < 8; r++) {
        int rr = row0 + r; if (rr >= NN) rr = NN - 1;
        xr[r] = (const float4*)(x + (size_t)rr * DIMK);
    }

    unsigned long long acc[4][4];
#pragma unroll
    for (int rp = 0; rp < 4; rp++)
#pragma unroll
        for (int c = 0; c < 4; c++) acc[rp][c] = 0ull;

#pragma unroll 4
    for (int kq = 0; kq < DIMK / 4; kq++) {
        float4 xv[8];
#pragma unroll
        for (int r = 0; r < 8; r++) xv[r] = xr[r][kq];   // dedup'd LDG.128

#pragma unroll
        for (int kk = 0; kk < 4; kk++) {
            float4 wv = *(const float4*)&Ws[4 * kq + kk][4 * cg];  // broadcast LDS
            unsigned long long wd[4];
            wd[0] = pk2(wv.x, wv.x); wd[1] = pk2(wv.y, wv.y);
            wd[2] = pk2(wv.z, wv.z); wd[3] = pk2(wv.w, wv.w);
#pragma unroll
            for (int rp = 0; rp < 4; rp++) {
                float a = (kk == 0) ? xv[2*rp].x : (kk == 1) ? xv[2*rp].y
                         : (kk == 2) ? xv[2*rp].z : xv[2*rp].w;
                float bq = (kk == 0) ? xv[2*rp+1].x : (kk == 1) ? xv[2*rp+1].y
                         : (kk == 2) ? xv[2*rp+1].z : xv[2*rp+1].w;
                unsigned long long xp = pk2(a, bq);
#pragma unroll
                for (int c = 0; c < 4; c++) ffma2(acc[rp][c], xp, wd[c]);
            }
        }
    }

#pragma unroll
    for (int rp = 0; rp < 4; rp++) {
        float h0[4], h1[4];
#pragma unroll
        for (int c = 0; c < 4; c++) upk2(acc[rp][c], h0[c], h1[c]);
#pragma unroll
        for (int half_ = 0; half_ < 2; half_++) {
            int row = row0 + 2 * rp + half_;
            if (row < NN) {
                float* hv = half_ ? h1 : h0;
                float di = rsqrtf((float)g_cur[row] + 1.0f);   // inline dinv
                float4 hs4 = make_float4(hv[0]*di, hv[1]*di, hv[2]*di, hv[3]*di);
                *(float4*)&g_agg[(size_t)row * NC + 4 * cg] = hs4;   // self-loop seed
                half2 p0 = __floats2half2_rn(hs4.x, hs4.y);
                half2 p1 = __floats2half2_rn(hs4.z, hs4.w);
                *(uint2*)&g_hs_h[(size_t)row * NC + 4 * cg] =
                    make_uint2(*(unsigned*)&p0, *(unsigned*)&p1);
            }
        }
    }
}

// ---------------------------------------------------------------- gather
// Warp per dst node, atomic-free, MLP-optimized: the node's src list is
// loaded in ONE coalesced LDG into lane registers, then payload loads are
// fully independent (4 lanes/edge, 8 edges in flight per pass).
__global__ void __launch_bounds__(256) k_gather() {
    int node = (blockIdx.x * blockDim.x + threadIdx.x) >> 5;
    if (node >= NN) return;
    int lane = threadIdx.x & 31;
    int g4 = lane >> 2;   // edge slot within pass (0..7)
    int l4 = lane & 3;    // channel quad: 8 channels = 16B

    size_t start = (size_t)node * CAP;
    int cnt = g_cur[node];
    if (cnt > CAP) cnt = CAP;   // overflow handled by k_fix

    const uint4* hs4 = (const uint4*)g_hs_h;   // 16B = 8 halves per load
    float a[8];
#pragma unroll
    for (int c = 0; c < 8; c++) a[c] = 0.0f;

    for (int base = 0; base < cnt; base += 32) {
        int m = cnt - base; if (m > 32) m = 32;
        int es = 0;
        if (lane < m) es = g_esrc[start + base + lane];   // one coalesced LDG
        int passes = (m + 7) >> 3;
#pragma unroll 4
        for (int p = 0; p < 4; p++) {
            if (p >= passes) break;
            int idx = p * 8 + g4;
            int sj = __shfl_sync(0xffffffffu, es, idx);
            if (idx < m) {
                uint4 hv = hs4[(size_t)sj * 4 + l4];      // independent LDG.128
                float2 f0 = __half22float2(*(half2*)&hv.x);
                float2 f1 = __half22float2(*(half2*)&hv.y);
                float2 f2 = __half22float2(*(half2*)&hv.z);
                float2 f3 = __half22float2(*(half2*)&hv.w);
                a[0] += f0.x; a[1] += f0.y; a[2] += f1.x; a[3] += f1.y;
                a[4] += f2.x; a[5] += f2.y; a[6] += f3.x; a[7] += f3.y;
            }
        }
    }

    // combine the 8 edge-subgroups (same l4): distances 16, 8, 4
#pragma unroll
    for (int c = 0; c < 8; c++) {
        a[c] += __shfl_down_sync(0xffffffffu, a[c], 16);
        a[c] += __shfl_down_sync(0xffffffffu, a[c], 8);
        a[c] += __shfl_down_sync(0xffffffffu, a[c], 4);
    }

    if (lane < 4) {   // lane == l4 owns channels [8*l4, 8*l4+8)
        float4* p0 = (float4*)&g_agg[(size_t)node * NC + 8 * lane];
        float4 s0 = p0[0], s1 = p0[1];     // gemm self-loop seed
        p0[0] = make_float4(s0.x + a[0], s0.y + a[1], s0.z + a[2], s0.w + a[3]);
        p0[1] = make_float4(s1.x + a[4], s1.y + a[5], s1.z + a[6], s1.w + a[7]);
    }
}

// ---------------------------------------------------------------- overflow fixup
// Expected empty; exact-correctness safety net for CAP overflow.
__global__ void k_fix() {
    int n = g_ovfn;
    if (n > OVFCAP) n = OVFCAP;
    int lane = threadIdx.x & 31;
    int g  = lane >> 3;
    int l8 = lane & 7;
    const uint2* hs2 = (const uint2*)g_hs_h;
    int wid = (blockIdx.x * blockDim.x + threadIdx.x) >> 5;
    int nw  = (gridDim.x * blockDim.x) >> 5;
    for (int j = wid * 4 + g; j < n; j += nw * 4) {
        int2 e = g_ovf[j];
        uint2 hv = hs2[(size_t)e.x * 8 + l8];
        float2 fa = __half22float2(*(half2*)&hv.x);
        float2 fb = __half22float2(*(half2*)&hv.y);
        float* p = &g_agg[(size_t)e.y * NC + l8 * 4];
        asm volatile("red.global.add.v4.f32 [%0], {%1, %2, %3, %4};"
                     :: "l"(p), "f"(fa.x), "f"(fa.y), "f"(fb.x), "f"(fb.y)
                     : "memory");
    }
}

// ---------------------------------------------------------------- pooling
__global__ void __launch_bounds__(256) k_pool(const int* __restrict__ batch) {
    __shared__ float sp[NG * NC];
    __shared__ float sc[NG];
    int tid = threadIdx.x;
    for (int i = tid; i < NG * NC; i += 256) sp[i] = 0.0f;
    if (tid < NG) sc[tid] = 0.0f;
    __syncthreads();

    int warp = tid >> 5, lane = tid & 31;
    int wid = blockIdx.x * 8 + warp;
    int nwarps = gridDim.x * 8;
    int per = (NN + nwarps - 1) / nwarps;
    int s0 = wid * per;
    int s1 = min(NN, s0 + per);

    float acc = 0.0f, cacc = 0.0f;
    int curg = -1;
    for (int i = s0; i < s1; i++) {
        int gidx = __ldg(&batch[i]);
        if (gidx != curg) {
            if (curg >= 0) {
                atomicAdd(&sp[curg * NC + lane], acc);
                if (lane == 0) atomicAdd(&sc[curg], cacc);
            }
            curg = gidx; acc = 0.0f; cacc = 0.0f;
        }
        float di = rsqrtf((float)g_cur[i] + 1.0f);   // inline dinv
        acc  += g_agg[(size_t)i * NC + lane] * di;
        cacc += 1.0f;
    }
    if (curg >= 0) {
        atomicAdd(&sp[curg * NC + lane], acc);
        if (lane == 0) atomicAdd(&sc[curg], cacc);
    }
    __syncthreads();

    for (int i = tid; i < NG * NC; i += 256) atomicAdd(&g_pool[i], sp[i]);
    if (tid < NG) atomicAdd(&g_cnt[tid], sc[tid]);
}

// ---------------------------------------------------------------- finalize
__global__ void k_final(const float* __restrict__ b, float* __restrict__ out) {
    int i = blockIdx.x * blockDim.x + threadIdx.x;
    if (i < NG * NC) {
        int g = i >> 5, c = i & 31;
        float cnt = g_cnt[g];
        out[i] = (cnt > 0.0f) ? (g_pool[i] / cnt + b[c]) : 0.0f;
    }
}

// ---------------------------------------------------------------- launch
extern "C" void kernel_launch(void* const* d_in, const int* in_sizes, int n_in,
                              void* d_out, int out_size) {
    const float* x     = (const float*)d_in[0];
    const float* W     = (const float*)d_in[1];
    const float* b     = (const float*)d_in[2];
    const int*   ei    = (const int*)d_in[3];
    const int*   batch = (const int*)d_in[4];
    float*       out   = (float*)d_out;

    const int* src = ei;        // edge_index[0]
    const int* dst = ei + NE;   // edge_index[1]

    k_zero <<<(NN + 255) / 256, 256>>>();
    k_build<<<(NE / 4 + 255) / 256, 256>>>(src, dst);
    k_gemm <<<(NN + BR - 1) / BR, 256>>>(x, W);
    k_gather<<<(NN + 7) / 8, 256>>>();            // launch slot 4 -> ncu
    k_fix  <<<16, 256>>>();
    k_pool <<<64, 256>>>(batch);
    k_final<<<(NG * NC + 255) / 256, 256>>>(b, out);
}

// round 9
// speedup vs baseline: 1.4812x; 1.3280x over previous
#include <cuda_runtime.h>
#include <cuda_fp16.h>

#define NN 100000
#define NE 3200000
#define DIMK 256
#define NC 32
#define NG 64
#define BR 256     // rows per block in gemm
#define CAP 96     // fixed CSR stride (deg ~ Poisson(32); P(>=96) ~ 1e-18)
#define OVFCAP 8192
#define PBLK 256   // pool blocks

// Scratch (device globals; no allocation allowed)
__device__ int    g_cur[NN];                      // build cursor == final in-degree
__device__ int    g_esrc[(size_t)NN * CAP];       // fixed-stride CSR src lists (38.4MB)
__device__ int2   g_ovf[OVFCAP];                  // overflow edges (expected: none)
__device__ int    g_ovfn;
__device__ __half g_hs_h[(size_t)NN * NC];        // h * dinv[row] fp16 gather payload
__device__ float  g_agg[(size_t)NN * NC];         // self seed + edge sums (f32)
__device__ float  g_pool[NG * NC];
__device__ float  g_cnt[NG];

// f32x2 packed helpers (Blackwell packed fp32)
__device__ __forceinline__ unsigned long long pk2(float a, float b) {
    unsigned long long r;
    asm("mov.b64 %0, {%1, %2};" : "=l"(r) : "f"(a), "f"(b));
    return r;
}
__device__ __forceinline__ void ffma2(unsigned long long& d, unsigned long long a,
                                      unsigned long long b) {
    asm("fma.rn.f32x2 %0, %1, %2, %0;" : "+l"(d) : "l"(a), "l"(b));
}
__device__ __forceinline__ void upk2(unsigned long long v, float& lo, float& hi) {
    asm("mov.b64 {%0, %1}, %2;" : "=f"(lo), "=f"(hi) : "l"(v));
}

// ---------------------------------------------------------------- zero
__global__ void k_zero() {
    int i = blockIdx.x * blockDim.x + threadIdx.x;
    if (i < NN) g_cur[i] = 0;
    if (i < NG * NC) g_pool[i] = 0.0f;
    if (i < NG) g_cnt[i] = 0.0f;
    if (i == 0) g_ovfn = 0;
}

// ---------------------------------------------------------------- CSR build
__global__ void k_build(const int* __restrict__ src, const int* __restrict__ dst) {
    int i = blockIdx.x * blockDim.x + threadIdx.x;
    if (i * 4 < NE) {
        int4 s = ((const int4*)src)[i];
        int4 d = ((const int4*)dst)[i];
#pragma unroll
        for (int k = 0; k < 4; k++) {
            int dd = (k == 0) ? d.x : (k == 1) ? d.y : (k == 2) ? d.z : d.w;
            int ss = (k == 0) ? s.x : (k == 1) ? s.y : (k == 2) ? s.z : s.w;
            int p = atomicAdd(&g_cur[dd], 1);
            if (p < CAP) {
                g_esrc[(size_t)dd * CAP + p] = ss;
            } else {
                int q = atomicAdd(&g_ovfn, 1);
                if (q < OVFCAP) g_ovf[q] = make_int2(ss, dd);
            }
        }
    }
}

// ---------------------------------------------------------------- GEMM + self term
__global__ void __launch_bounds__(256, 2) k_gemm(const float* __restrict__ x,
                                                 const float* __restrict__ W) {
    __shared__ float Ws[DIMK][NC];   // 32KB

    int tid = threadIdx.x, warp = tid >> 5, lane = tid & 31;

    for (int i = tid; i < DIMK * NC / 4; i += 256)
        ((float4*)Ws)[i] = ((const float4*)W)[i];
    __syncthreads();

    int cg = lane & 7;    // col group: cols 4cg..4cg+3
    int rg = lane >> 3;   // row group: 8 rows
    int row0 = blockIdx.x * BR + warp * 32 + rg * 8;

    const float4* xr[8];
#pragma unroll
    for (int r = 0; r < 8; r++) {
        int rr = row0 + r; if (rr >= NN) rr = NN - 1;
        xr[r] = (const float4*)(x + (size_t)rr * DIMK);
    }

    unsigned long long acc[4][4];
#pragma unroll
    for (int rp = 0; rp < 4; rp++)
#pragma unroll
        for (int c = 0; c < 4; c++) acc[rp][c] = 0ull;

#pragma unroll 4
    for (int kq = 0; kq < DIMK / 4; kq++) {
        float4 xv[8];
#pragma unroll
        for (int r = 0; r < 8; r++) xv[r] = xr[r][kq];   // dedup'd LDG.128

#pragma unroll
        for (int kk = 0; kk < 4; kk++) {
            float4 wv = *(const float4*)&Ws[4 * kq + kk][4 * cg];  // broadcast LDS
            unsigned long long wd[4];
            wd[0] = pk2(wv.x, wv.x); wd[1] = pk2(wv.y, wv.y);
            wd[2] = pk2(wv.z, wv.z); wd[3] = pk2(wv.w, wv.w);
#pragma unroll
            for (int rp = 0; rp < 4; rp++) {
                float a = (kk == 0) ? xv[2*rp].x : (kk == 1) ? xv[2*rp].y
                         : (kk == 2) ? xv[2*rp].z : xv[2*rp].w;
                float bq = (kk == 0) ? xv[2*rp+1].x : (kk == 1) ? xv[2*rp+1].y
                         : (kk == 2) ? xv[2*rp+1].z : xv[2*rp+1].w;
                unsigned long long xp = pk2(a, bq);
#pragma unroll
                for (int c = 0; c < 4; c++) ffma2(acc[rp][c], xp, wd[c]);
            }
        }
    }

#pragma unroll
    for (int rp = 0; rp < 4; rp++) {
        float h0[4], h1[4];
#pragma unroll
        for (int c = 0; c < 4; c++) upk2(acc[rp][c], h0[c], h1[c]);
#pragma unroll
        for (int half_ = 0; half_ < 2; half_++) {
            int row = row0 + 2 * rp + half_;
            if (row < NN) {
                float* hv = half_ ? h1 : h0;
                float di = rsqrtf((float)g_cur[row] + 1.0f);   // inline dinv
                float4 hs4 = make_float4(hv[0]*di, hv[1]*di, hv[2]*di, hv[3]*di);
                *(float4*)&g_agg[(size_t)row * NC + 4 * cg] = hs4;   // self-loop seed
                half2 p0 = __floats2half2_rn(hs4.x, hs4.y);
                half2 p1 = __floats2half2_rn(hs4.z, hs4.w);
                *(uint2*)&g_hs_h[(size_t)row * NC + 4 * cg] =
                    make_uint2(*(unsigned*)&p0, *(unsigned*)&p1);
            }
        }
    }
}

// ---------------------------------------------------------------- gather
// Warp per dst node, atomic-free, MLP-optimized.
__global__ void __launch_bounds__(256) k_gather() {
    int node = (blockIdx.x * blockDim.x + threadIdx.x) >> 5;
    if (node >= NN) return;
    int lane = threadIdx.x & 31;
    int g4 = lane >> 2;   // edge slot within pass (0..7)
    int l4 = lane & 3;    // channel quad: 8 channels = 16B

    size_t start = (size_t)node * CAP;
    int cnt = g_cur[node];
    if (cnt > CAP) cnt = CAP;   // overflow handled by k_fix

    const uint4* hs4 = (const uint4*)g_hs_h;   // 16B = 8 halves per load
    float a[8];
#pragma unroll
    for (int c = 0; c < 8; c++) a[c] = 0.0f;

    for (int base = 0; base < cnt; base += 32) {
        int m = cnt - base; if (m > 32) m = 32;
        int es = 0;
        if (lane < m) es = g_esrc[start + base + lane];   // one coalesced LDG
        int passes = (m + 7) >> 3;
#pragma unroll 4
        for (int p = 0; p < 4; p++) {
            if (p >= passes) break;
            int idx = p * 8 + g4;
            int sj = __shfl_sync(0xffffffffu, es, idx);
            if (idx < m) {
                uint4 hv = hs4[(size_t)sj * 4 + l4];      // independent LDG.128
                float2 f0 = __half22float2(*(half2*)&hv.x);
                float2 f1 = __half22float2(*(half2*)&hv.y);
                float2 f2 = __half22float2(*(half2*)&hv.z);
                float2 f3 = __half22float2(*(half2*)&hv.w);
                a[0] += f0.x; a[1] += f0.y; a[2] += f1.x; a[3] += f1.y;
                a[4] += f2.x; a[5] += f2.y; a[6] += f3.x; a[7] += f3.y;
            }
        }
    }

#pragma unroll
    for (int c = 0; c < 8; c++) {
        a[c] += __shfl_down_sync(0xffffffffu, a[c], 16);
        a[c] += __shfl_down_sync(0xffffffffu, a[c], 8);
        a[c] += __shfl_down_sync(0xffffffffu, a[c], 4);
    }

    if (lane < 4) {   // lane == l4 owns channels [8*l4, 8*l4+8)
        float4* p0 = (float4*)&g_agg[(size_t)node * NC + 8 * lane];
        float4 s0 = p0[0], s1 = p0[1];     // gemm self-loop seed
        p0[0] = make_float4(s0.x + a[0], s0.y + a[1], s0.z + a[2], s0.w + a[3]);
        p0[1] = make_float4(s1.x + a[4], s1.y + a[5], s1.z + a[6], s1.w + a[7]);
    }
}

// ---------------------------------------------------------------- overflow fixup
__global__ void k_fix() {
    int n = g_ovfn;
    if (n > OVFCAP) n = OVFCAP;
    int lane = threadIdx.x & 31;
    int g  = lane >> 3;
    int l8 = lane & 7;
    const uint2* hs2 = (const uint2*)g_hs_h;
    int wid = (blockIdx.x * blockDim.x + threadIdx.x) >> 5;
    int nw  = (gridDim.x * blockDim.x) >> 5;
    for (int j = wid * 4 + g; j < n; j += nw * 4) {
        int2 e = g_ovf[j];
        uint2 hv = hs2[(size_t)e.x * 8 + l8];
        float2 fa = __half22float2(*(half2*)&hv.x);
        float2 fb = __half22float2(*(half2*)&hv.y);
        float* p = &g_agg[(size_t)e.y * NC + l8 * 4];
        asm volatile("red.global.add.v4.f32 [%0], {%1, %2, %3, %4};"
                     :: "l"(p), "f"(fa.x), "f"(fa.y), "f"(fb.x), "f"(fb.y)
                     : "memory");
    }
}

// ---------------------------------------------------------------- pooling
// 256 blocks, MLP-4 pipelined loads, range-tracked flush.
__global__ void __launch_bounds__(256) k_pool(const int* __restrict__ batch) {
    __shared__ float sp[NG * NC];
    __shared__ float sc[NG];
    __shared__ int gmin, gmax;
    int tid = threadIdx.x;
    for (int i = tid; i < NG * NC; i += 256) sp[i] = 0.0f;
    if (tid < NG) sc[tid] = 0.0f;
    if (tid == 0) { gmin = NG; gmax = -1; }
    __syncthreads();

    int warp = tid >> 5, lane = tid & 31;
    int wid = blockIdx.x * 8 + warp;
    int nwarps = PBLK * 8;
    int per = (NN + nwarps - 1) / nwarps;
    int s0 = wid * per;
    int s1 = min(NN, s0 + per);

    float acc = 0.0f, cacc = 0.0f;
    int curg = -1, firstg = NG, lastg = -1;

    for (int i = s0; i < s1; i += 4) {
        int m = s1 - i; if (m > 4) m = 4;
        // issue all loads up-front (MLP=4 x 3 streams)
        int   bb[4];
        float vv[4];
        float dd[4];
#pragma unroll
        for (int k = 0; k < 4; k++) {
            if (k < m) {
                bb[k] = __ldg(&batch[i + k]);
                vv[k] = g_agg[(size_t)(i + k) * NC + lane];
                dd[k] = (float)g_cur[i + k];
            }
        }
#pragma unroll
        for (int k = 0; k < 4; k++) {
            if (k < m) {
                if (bb[k] != curg) {
                    if (curg >= 0) {
                        atomicAdd(&sp[curg * NC + lane], acc);
                        if (lane == 0) atomicAdd(&sc[curg], cacc);
                    }
                    curg = bb[k]; acc = 0.0f; cacc = 0.0f;
                    if (curg < firstg) firstg = curg;
                    if (curg > lastg)  lastg = curg;
                }
                acc  += vv[k] * rsqrtf(dd[k] + 1.0f);
                cacc += 1.0f;
            }
        }
    }
    if (curg >= 0) {
        atomicAdd(&sp[curg * NC + lane], acc);
        if (lane == 0) atomicAdd(&sc[curg], cacc);
    }
    if (lane == 0 && lastg >= 0) {
        atomicMin(&gmin, firstg);
        atomicMax(&gmax, lastg);
    }
    __syncthreads();

    // flush only the touched graph range (typically 1-3 graphs)
    int lo = gmin, hi = gmax;
    if (hi >= lo) {
        for (int i = lo * NC + tid; i < (hi + 1) * NC; i += 256)
            atomicAdd(&g_pool[i], sp[i]);
        for (int g = lo + tid; g <= hi; g += 256)
            atomicAdd(&g_cnt[g], sc[g]);
    }
}

// ---------------------------------------------------------------- finalize
__global__ void k_final(const float* __restrict__ b, float* __restrict__ out) {
    int i = blockIdx.x * blockDim.x + threadIdx.x;
    if (i < NG * NC) {
        int g = i >> 5, c = i & 31;
        float cnt = g_cnt[g];
        out[i] = (cnt > 0.0f) ? (g_pool[i] / cnt + b[c]) : 0.0f;
    }
}

// ---------------------------------------------------------------- launch
extern "C" void kernel_launch(void* const* d_in, const int* in_sizes, int n_in,
                              void* d_out, int out_size) {
    const float* x     = (const float*)d_in[0];
    const float* W     = (const float*)d_in[1];
    const float* b     = (const float*)d_in[2];
    const int*   ei    = (const int*)d_in[3];
    const int*   batch = (const int*)d_in[4];
    float*       out   = (float*)d_out;

    const int* src = ei;        // edge_index[0]
    const int* dst = ei + NE;   // edge_index[1]

    k_zero <<<(NN + 255) / 256, 256>>>();
    k_build<<<(NE / 4 + 255) / 256, 256>>>(src, dst);
    k_gemm <<<(NN + BR - 1) / BR, 256>>>(x, W);
    k_gather<<<(NN + 7) / 8, 256>>>();
    k_fix  <<<16, 256>>>();
    k_pool <<<PBLK, 256>>>(batch);
    k_final<<<(NG * NC + 255) / 256, 256>>>(b, out);
}

// round 11
// speedup vs baseline: 1.5194x; 1.0258x over previous
#include <cuda_runtime.h>
#include <cuda_fp16.h>

#define NN 100000
#define NE 3200000
#define DIMK 256
#define NC 32
#define NG 64
#define CAP 96     // fixed CSR stride (deg ~ Poisson(32); P(>=96) ~ 1e-18)
#define OVFCAP 8192
#define PBLK 256   // pool blocks
#define GR 128     // rows per gemm block
#define RS 36      // stage row stride (floats): 144B -> conflict-free ldmatrix
#define GSMEM (2 * GR * RS * 4 + 2 * 8192 * 4)   // 36864 + 65536 = 102400B

// Scratch (device globals; no allocation allowed)
__device__ int    g_cur[NN];                      // build cursor == final in-degree
__device__ int    g_esrc[(size_t)NN * CAP];       // fixed-stride CSR src lists
__device__ int2   g_ovf[OVFCAP];
__device__ int    g_ovfn;
__device__ __half g_hs_h[(size_t)NN * NC];        // h * dinv fp16 gather payload
__device__ float  g_agg[(size_t)NN * NC];         // self seed + edge sums (f32)
__device__ float  g_pool[NG * NC];
__device__ float  g_cnt[NG];

__device__ __forceinline__ float to_tf32(float v) {
    unsigned r;
    asm("cvt.rna.tf32.f32 %0, %1;" : "=r"(r) : "f"(v));   // b32 dst (required)
    return __uint_as_float(r);
}
__device__ __forceinline__ void ldsm4(unsigned a[4], unsigned addr) {
    asm volatile("ldmatrix.sync.aligned.m8n8.x4.shared.b16 {%0,%1,%2,%3}, [%4];"
                 : "=r"(a[0]), "=r"(a[1]), "=r"(a[2]), "=r"(a[3]) : "r"(addr));
}
__device__ __forceinline__ void mma8(float c[4], const unsigned a[4],
                                     unsigned b0, unsigned b1) {
    asm volatile("mma.sync.aligned.m16n8k8.row.col.f32.tf32.tf32.f32 "
                 "{%0,%1,%2,%3}, {%4,%5,%6,%7}, {%8,%9}, {%0,%1,%2,%3};"
                 : "+f"(c[0]), "+f"(c[1]), "+f"(c[2]), "+f"(c[3])
                 : "r"(a[0]), "r"(a[1]), "r"(a[2]), "r"(a[3]), "r"(b0), "r"(b1));
}

// ---------------------------------------------------------------- zero (1)
__global__ void k_zero() {
    int i = blockIdx.x * blockDim.x + threadIdx.x;
    if (i < NN) g_cur[i] = 0;
    if (i == 0) g_ovfn = 0;
}

// ---------------------------------------------------------------- CSR build (2)
__global__ void k_build(const int* __restrict__ src, const int* __restrict__ dst) {
    int i = blockIdx.x * blockDim.x + threadIdx.x;
    if (i * 4 < NE) {
        int4 s = ((const int4*)src)[i];
        int4 d = ((const int4*)dst)[i];
#pragma unroll
        for (int k = 0; k < 4; k++) {
            int dd = (k == 0) ? d.x : (k == 1) ? d.y : (k == 2) ? d.z : d.w;
            int ss = (k == 0) ? s.x : (k == 1) ? s.y : (k == 2) ? s.z : s.w;
            int p = atomicAdd(&g_cur[dd], 1);
            if (p < CAP) {
                g_esrc[(size_t)dd * CAP + p] = ss;
            } else {
                int q = atomicAdd(&g_ovfn, 1);
                if (q < OVFCAP) g_ovf[q] = make_int2(ss, dd);
            }
        }
    }
}

// ---------------------------------------------------------------- pad/zero2 (3)
__global__ void k_zero2() {
    int i = blockIdx.x * blockDim.x + threadIdx.x;
    if (i < NG * NC) g_pool[i] = 0.0f;
    if (i < NG) g_cnt[i] = 0.0f;
}

// ---------------------------------------------------------------- GEMM (4, ncu)
// tf32 mma.m16n8k8, 3-term hi/lo split (xh*Wh + xh*Wl + xl*Wh).
// Warp = 16 rows; block = 8 warps = 128 rows. K chunked by 32 floats.
__global__ void __launch_bounds__(256) k_gemm(const float* __restrict__ x,
                                              const float* __restrict__ W) {
    extern __shared__ float sm[];
    float* sh = sm;                    // stage hi [128][36]
    float* sl = sm + GR * RS;          // stage lo [128][36]
    float* wf = sm + 2 * GR * RS;      // W frags [2 ver][32 kstep][2 ntp][32 lane][4]

    int tid = threadIdx.x, w = tid >> 5, lane = tid & 31;
    int row0g = blockIdx.x * GR;

    // One-time: pre-fragment W (hi & lo) in mma B-fragment order.
    for (int e = tid; e < 8192; e += 256) {
        int kstep = e >> 8;
        int rem   = e & 255;
        int ntp   = rem >> 7;
        int rem2  = rem & 127;
        int ln    = rem2 >> 2;
        int j     = rem2 & 3;
        int nt = ntp * 2 + (j >> 1);
        int b  = j & 1;
        int k  = kstep * 8 + (ln & 3) + b * 4;
        int n  = nt * 8 + (ln >> 2);
        float v  = W[k * NC + n];
        float hi = to_tf32(v);
        float lo = to_tf32(v - hi);
        int off = ((kstep * 2 + ntp) * 32 + ln) * 4 + j;
        wf[off]        = hi;
        wf[8192 + off] = lo;
    }

    float c[4][4];
#pragma unroll
    for (int nt = 0; nt < 4; nt++)
#pragma unroll
        for (int q = 0; q < 4; q++) c[nt][q] = 0.0f;

    const float4* x4 = (const float4*)x;

    for (int cc = 0; cc < 8; cc++) {
        __syncthreads();   // protect stage from previous iteration readers
        // Stage 128 rows x 32 k floats, split hi/lo
#pragma unroll
        for (int t = 0; t < 4; t++) {
            int f = tid + t * 256;       // 0..1023
            int row = f >> 3, q = f & 7;
            int rr = row0g + row; if (rr >= NN) rr = NN - 1;
            float4 v = x4[(size_t)rr * (DIMK / 4) + cc * 8 + q];
            float4 h, l;
            h.x = to_tf32(v.x); l.x = to_tf32(v.x - h.x);
            h.y = to_tf32(v.y); l.y = to_tf32(v.y - h.y);
            h.z = to_tf32(v.z); l.z = to_tf32(v.z - h.z);
            h.w = to_tf32(v.w); l.w = to_tf32(v.w - h.w);
            *(float4*)&sh[row * RS + q * 4] = h;
            *(float4*)&sl[row * RS + q * 4] = l;
        }
        __syncthreads();

#pragma unroll
        for (int ks = 0; ks < 4; ks++) {
            int kstep = cc * 4 + ks;
            int soff = (w * 16 + (lane & 15)) * RS + ks * 8 + (lane >> 4) * 4;
            unsigned ah[4], al[4];
            ldsm4(ah, (unsigned)__cvta_generic_to_shared(&sh[soff]));
            ldsm4(al, (unsigned)__cvta_generic_to_shared(&sl[soff]));
#pragma unroll
            for (int ntp = 0; ntp < 2; ntp++) {
                int boff = ((kstep * 2 + ntp) * 32 + lane) * 4;
                uint4 wh = *(uint4*)&wf[boff];
                uint4 wl = *(uint4*)&wf[8192 + boff];
                mma8(c[2 * ntp],     ah, wh.x, wh.y);
                mma8(c[2 * ntp],     ah, wl.x, wl.y);
                mma8(c[2 * ntp],     al, wh.x, wh.y);
                mma8(c[2 * ntp + 1], ah, wh.z, wh.w);
                mma8(c[2 * ntp + 1], ah, wl.z, wl.w);
                mma8(c[2 * ntp + 1], al, wh.z, wh.w);
            }
        }
    }

    // Epilogue: c0,c1 -> row g; c2,c3 -> row g+8; cols nt*8 + 2t,2t+1
    int g = lane >> 2, t = lane & 3;
#pragma unroll
    for (int rh = 0; rh < 2; rh++) {
        int row = row0g + w * 16 + g + rh * 8;
        if (row < NN) {
            float di = rsqrtf((float)g_cur[row] + 1.0f);
#pragma unroll
            for (int nt = 0; nt < 4; nt++) {
                float v0 = c[nt][rh * 2 + 0] * di;
                float v1 = c[nt][rh * 2 + 1] * di;
                int col = nt * 8 + 2 * t;
                *(float2*)&g_agg[(size_t)row * NC + col] = make_float2(v0, v1);
                half2 hp = __floats2half2_rn(v0, v1);
                *(unsigned*)&g_hs_h[(size_t)row * NC + col] = *(unsigned*)&hp;
            }
        }
    }
}

// ---------------------------------------------------------------- gather (5)
__global__ void __launch_bounds__(256) k_gather() {
    int node = (blockIdx.x * blockDim.x + threadIdx.x) >> 5;
    if (node >= NN) return;
    int lane = threadIdx.x & 31;
    int g4 = lane >> 2;
    int l4 = lane & 3;

    size_t start = (size_t)node * CAP;
    int cnt = g_cur[node];
    if (cnt > CAP) cnt = CAP;

    const uint4* hs4 = (const uint4*)g_hs_h;
    float a[8];
#pragma unroll
    for (int c = 0; c < 8; c++) a[c] = 0.0f;

    for (int base = 0; base < cnt; base += 32) {
        int m = cnt - base; if (m > 32) m = 32;
        int es = 0;
        if (lane < m) es = g_esrc[start + base + lane];
        int passes = (m + 7) >> 3;
#pragma unroll 4
        for (int p = 0; p < 4; p++) {
            if (p >= passes) break;
            int idx = p * 8 + g4;
            int sj = __shfl_sync(0xffffffffu, es, idx);
            if (idx < m) {
                uint4 hv = hs4[(size_t)sj * 4 + l4];
                float2 f0 = __half22float2(*(half2*)&hv.x);
                float2 f1 = __half22float2(*(half2*)&hv.y);
                float2 f2 = __half22float2(*(half2*)&hv.z);
                float2 f3 = __half22float2(*(half2*)&hv.w);
                a[0] += f0.x; a[1] += f0.y; a[2] += f1.x; a[3] += f1.y;
                a[4] += f2.x; a[5] += f2.y; a[6] += f3.x; a[7] += f3.y;
            }
        }
    }

#pragma unroll
    for (int c = 0; c < 8; c++) {
        a[c] += __shfl_down_sync(0xffffffffu, a[c], 16);
        a[c] += __shfl_down_sync(0xffffffffu, a[c], 8);
        a[c] += __shfl_down_sync(0xffffffffu, a[c], 4);
    }

    if (lane < 4) {
        float4* p0 = (float4*)&g_agg[(size_t)node * NC + 8 * lane];
        float4 s0 = p0[0], s1 = p0[1];
        p0[0] = make_float4(s0.x + a[0], s0.y + a[1], s0.z + a[2], s0.w + a[3]);
        p0[1] = make_float4(s1.x + a[4], s1.y + a[5], s1.z + a[6], s1.w + a[7]);
    }
}

// ---------------------------------------------------------------- fixup (6)
__global__ void k_fix() {
    int n = g_ovfn;
    if (n > OVFCAP) n = OVFCAP;
    int lane = threadIdx.x & 31;
    int g  = lane >> 3;
    int l8 = lane & 7;
    const uint2* hs2 = (const uint2*)g_hs_h;
    int wid = (blockIdx.x * blockDim.x + threadIdx.x) >> 5;
    int nw  = (gridDim.x * blockDim.x) >> 5;
    for (int j = wid * 4 + g; j < n; j += nw * 4) {
        int2 e = g_ovf[j];
        uint2 hv = hs2[(size_t)e.x * 8 + l8];
        float2 fa = __half22float2(*(half2*)&hv.x);
        float2 fb = __half22float2(*(half2*)&hv.y);
        float* p = &g_agg[(size_t)e.y * NC + l8 * 4];
        asm volatile("red.global.add.v4.f32 [%0], {%1, %2, %3, %4};"
                     :: "l"(p), "f"(fa.x), "f"(fa.y), "f"(fb.x), "f"(fb.y)
                     : "memory");
    }
}

// ---------------------------------------------------------------- pooling (7)
__global__ void __launch_bounds__(256) k_pool(const int* __restrict__ batch) {
    __shared__ float sp[NG * NC];
    __shared__ float sc[NG];
    __shared__ int gmin, gmax;
    int tid = threadIdx.x;
    for (int i = tid; i < NG * NC; i += 256) sp[i] = 0.0f;
    if (tid < NG) sc[tid] = 0.0f;
    if (tid == 0) { gmin = NG; gmax = -1; }
    __syncthreads();

    int warp = tid >> 5, lane = tid & 31;
    int wid = blockIdx.x * 8 + warp;
    int nwarps = PBLK * 8;
    int per = (NN + nwarps - 1) / nwarps;
    int s0 = wid * per;
    int s1 = min(NN, s0 + per);

    float acc = 0.0f, cacc = 0.0f;
    int curg = -1, firstg = NG, lastg = -1;

    for (int i = s0; i < s1; i += 4) {
        int m = s1 - i; if (m > 4) m = 4;
        int   bb[4];
        float vv[4];
        float dd[4];
#pragma unroll
        for (int k = 0; k < 4; k++) {
            if (k < m) {
                bb[k] = __ldg(&batch[i + k]);
                vv[k] = g_agg[(size_t)(i + k) * NC + lane];
                dd[k] = (float)g_cur[i + k];
            }
        }
#pragma unroll
        for (int k = 0; k < 4; k++) {
            if (k < m) {
                if (bb[k] != curg) {
                    if (curg >= 0) {
                        atomicAdd(&sp[curg * NC + lane], acc);
                        if (lane == 0) atomicAdd(&sc[curg], cacc);
                    }
                    curg = bb[k]; acc = 0.0f; cacc = 0.0f;
                    if (curg < firstg) firstg = curg;
                    if (curg > lastg)  lastg = curg;
                }
                acc  += vv[k] * rsqrtf(dd[k] + 1.0f);
                cacc += 1.0f;
            }
        }
    }
    if (curg >= 0) {
        atomicAdd(&sp[curg * NC + lane], acc);
        if (lane == 0) atomicAdd(&sc[curg], cacc);
    }
    if (lane == 0 && lastg >= 0) {
        atomicMin(&gmin, firstg);
        atomicMax(&gmax, lastg);
    }
    __syncthreads();

    int lo = gmin, hi = gmax;
    if (hi >= lo) {
        for (int i = lo * NC + tid; i < (hi + 1) * NC; i += 256)
            atomicAdd(&g_pool[i], sp[i]);
        for (int g = lo + tid; g <= hi; g += 256)
            atomicAdd(&g_cnt[g], sc[g]);
    }
}

// ---------------------------------------------------------------- finalize (8)
__global__ void k_final(const float* __restrict__ b, float* __restrict__ out) {
    int i = blockIdx.x * blockDim.x + threadIdx.x;
    if (i < NG * NC) {
        int g = i >> 5, c = i & 31;
        float cnt = g_cnt[g];
        out[i] = (cnt > 0.0f) ? (g_pool[i] / cnt + b[c]) : 0.0f;
    }
}

// ---------------------------------------------------------------- launch
extern "C" void kernel_launch(void* const* d_in, const int* in_sizes, int n_in,
                              void* d_out, int out_size) {
    const float* x     = (const float*)d_in[0];
    const float* W     = (const float*)d_in[1];
    const float* b     = (const float*)d_in[2];
    const int*   ei    = (const int*)d_in[3];
    const int*   batch = (const int*)d_in[4];
    float*       out   = (float*)d_out;

    const int* src = ei;        // edge_index[0]
    const int* dst = ei + NE;   // edge_index[1]

    cudaFuncSetAttribute(k_gemm, cudaFuncAttributeMaxDynamicSharedMemorySize, GSMEM);

    k_zero <<<(NN + 255) / 256, 256>>>();
    k_build<<<(NE / 4 + 255) / 256, 256>>>(src, dst);
    k_zero2<<<(NG * NC + 255) / 256, 256>>>();
    k_gemm <<<(NN + GR - 1) / GR, 256, GSMEM>>>(x, W);     // slot 4 -> ncu
    k_gather<<<(NN + 7) / 8, 256>>>();
    k_fix  <<<16, 256>>>();
    k_pool <<<PBLK, 256>>>(batch);
    k_final<<<(NG * NC + 255) / 256, 256>>>(b, out);
}

// round 12
// speedup vs baseline: 1.5572x; 1.0249x over previous
#include <cuda_runtime.h>
#include <cuda_fp16.h>

#define NN 100000
#define NE 3200000
#define DIMK 256
#define NC 32
#define NG 64
#define CAP 96     // fixed CSR stride (deg ~ Poisson(32); P(>=96) ~ 1e-18)
#define OVFCAP 8192
#define PBLK 256   // pool blocks
#define GR 128     // rows per gemm block
#define GSMEM (2 * 8192 * 4)   // W fragments only: 64KB

// Scratch (device globals; no allocation allowed)
__device__ int    g_cur[NN];                      // build cursor == final in-degree
__device__ int    g_esrc[(size_t)NN * CAP];       // fixed-stride CSR src lists
__device__ int2   g_ovf[OVFCAP];
__device__ int    g_ovfn;
__device__ __half g_hs_h[(size_t)NN * NC];        // h * dinv fp16 gather payload
__device__ float  g_agg[(size_t)NN * NC];         // self seed + edge sums (f32)
__device__ float  g_pool[NG * NC];
__device__ float  g_cnt[NG];

__device__ __forceinline__ unsigned tf32_bits(float v) {
    unsigned r;
    asm("cvt.rna.tf32.f32 %0, %1;" : "=r"(r) : "f"(v));
    return r;
}
__device__ __forceinline__ float to_tf32(float v) {
    return __uint_as_float(tf32_bits(v));
}
__device__ __forceinline__ void mma8(float c[4], const unsigned a[4],
                                     unsigned b0, unsigned b1) {
    asm volatile("mma.sync.aligned.m16n8k8.row.col.f32.tf32.tf32.f32 "
                 "{%0,%1,%2,%3}, {%4,%5,%6,%7}, {%8,%9}, {%0,%1,%2,%3};"
                 : "+f"(c[0]), "+f"(c[1]), "+f"(c[2]), "+f"(c[3])
                 : "r"(a[0]), "r"(a[1]), "r"(a[2]), "r"(a[3]), "r"(b0), "r"(b1));
}

// ---------------------------------------------------------------- zero (1)
__global__ void k_zero() {
    int i = blockIdx.x * blockDim.x + threadIdx.x;
    if (i < NN) g_cur[i] = 0;
    if (i == 0) g_ovfn = 0;
}

// ---------------------------------------------------------------- CSR build (2)
__global__ void k_build(const int* __restrict__ src, const int* __restrict__ dst) {
    int i = blockIdx.x * blockDim.x + threadIdx.x;
    if (i * 4 < NE) {
        int4 s = ((const int4*)src)[i];
        int4 d = ((const int4*)dst)[i];
#pragma unroll
        for (int k = 0; k < 4; k++) {
            int dd = (k == 0) ? d.x : (k == 1) ? d.y : (k == 2) ? d.z : d.w;
            int ss = (k == 0) ? s.x : (k == 1) ? s.y : (k == 2) ? s.z : s.w;
            int p = atomicAdd(&g_cur[dd], 1);
            if (p < CAP) {
                g_esrc[(size_t)dd * CAP + p] = ss;
            } else {
                int q = atomicAdd(&g_ovfn, 1);
                if (q < OVFCAP) g_ovf[q] = make_int2(ss, dd);
            }
        }
    }
}

// ---------------------------------------------------------------- pad/zero2 (3)
__global__ void k_zero2() {
    int i = blockIdx.x * blockDim.x + threadIdx.x;
    if (i < NG * NC) g_pool[i] = 0.0f;
    if (i < NG) g_cnt[i] = 0.0f;
}

// ---------------------------------------------------------------- GEMM (4, ncu)
// tf32 mma.m16n8k8, 3-term hi/lo split. A-fragments loaded DIRECTLY from
// global per the documented lane layout (rows g,g+8; cols t,t+4) -- no x
// staging, no ldmatrix, no loop syncthreads. W pre-fragmented in smem.
__global__ void __launch_bounds__(256) k_gemm(const float* __restrict__ x,
                                              const float* __restrict__ W) {
    extern __shared__ float wf[];   // [2 ver][32 kstep][2 ntp][32 lane][4]

    int tid = threadIdx.x, w = tid >> 5, lane = tid & 31;
    int row0g = blockIdx.x * GR;

    // One-time: pre-fragment W (hi & lo) in mma B-fragment order.
    for (int e = tid; e < 8192; e += 256) {
        int kstep = e >> 8;
        int rem   = e & 255;
        int ntp   = rem >> 7;
        int rem2  = rem & 127;
        int ln    = rem2 >> 2;
        int j     = rem2 & 3;
        int nt = ntp * 2 + (j >> 1);
        int b  = j & 1;
        int k  = kstep * 8 + (ln & 3) + b * 4;
        int n  = nt * 8 + (ln >> 2);
        float v  = W[k * NC + n];
        float hi = to_tf32(v);
        float lo = to_tf32(v - hi);
        int off = ((kstep * 2 + ntp) * 32 + ln) * 4 + j;
        wf[off]        = hi;
        wf[8192 + off] = lo;
    }
    __syncthreads();

    int g = lane >> 2, t = lane & 3;
    int rowA = row0g + w * 16 + g;     if (rowA >= NN) rowA = NN - 1;
    int rowB = row0g + w * 16 + g + 8; if (rowB >= NN) rowB = NN - 1;
    const float* pA = x + (size_t)rowA * DIMK;
    const float* pB = x + (size_t)rowB * DIMK;

    float c[4][4];
#pragma unroll
    for (int nt = 0; nt < 4; nt++)
#pragma unroll
        for (int q = 0; q < 4; q++) c[nt][q] = 0.0f;

#pragma unroll 4
    for (int kstep = 0; kstep < 32; kstep++) {
        int k0 = kstep * 8 + t;
        float v0 = __ldg(pA + k0);
        float v1 = __ldg(pB + k0);
        float v2 = __ldg(pA + k0 + 4);
        float v3 = __ldg(pB + k0 + 4);

        unsigned ah[4], al[4];
        float h;
        h = to_tf32(v0); ah[0] = __float_as_uint(h); al[0] = tf32_bits(v0 - h);
        h = to_tf32(v1); ah[1] = __float_as_uint(h); al[1] = tf32_bits(v1 - h);
        h = to_tf32(v2); ah[2] = __float_as_uint(h); al[2] = tf32_bits(v2 - h);
        h = to_tf32(v3); ah[3] = __float_as_uint(h); al[3] = tf32_bits(v3 - h);

#pragma unroll
        for (int ntp = 0; ntp < 2; ntp++) {
            int boff = ((kstep * 2 + ntp) * 32 + lane) * 4;
            uint4 wh = *(uint4*)&wf[boff];
            uint4 wl = *(uint4*)&wf[8192 + boff];
            mma8(c[2 * ntp],     ah, wh.x, wh.y);
            mma8(c[2 * ntp],     ah, wl.x, wl.y);
            mma8(c[2 * ntp],     al, wh.x, wh.y);
            mma8(c[2 * ntp + 1], ah, wh.z, wh.w);
            mma8(c[2 * ntp + 1], ah, wl.z, wl.w);
            mma8(c[2 * ntp + 1], al, wh.z, wh.w);
        }
    }

    // Epilogue: c0,c1 -> row g; c2,c3 -> row g+8; cols nt*8 + 2t,2t+1
#pragma unroll
    for (int rh = 0; rh < 2; rh++) {
        int row = row0g + w * 16 + g + rh * 8;
        if (row < NN) {
            float di = rsqrtf((float)g_cur[row] + 1.0f);
#pragma unroll
            for (int nt = 0; nt < 4; nt++) {
                float v0 = c[nt][rh * 2 + 0] * di;
                float v1 = c[nt][rh * 2 + 1] * di;
                int col = nt * 8 + 2 * t;
                *(float2*)&g_agg[(size_t)row * NC + col] = make_float2(v0, v1);
                half2 hp = __floats2half2_rn(v0, v1);
                *(unsigned*)&g_hs_h[(size_t)row * NC + col] = *(unsigned*)&hp;
            }
        }
    }
}

// ---------------------------------------------------------------- gather (5)
__global__ void __launch_bounds__(256) k_gather() {
    int node = (blockIdx.x * blockDim.x + threadIdx.x) >> 5;
    if (node >= NN) return;
    int lane = threadIdx.x & 31;
    int g4 = lane >> 2;
    int l4 = lane & 3;

    size_t start = (size_t)node * CAP;
    int cnt = g_cur[node];
    if (cnt > CAP) cnt = CAP;

    const uint4* hs4 = (const uint4*)g_hs_h;
    float a[8];
#pragma unroll
    for (int c = 0; c < 8; c++) a[c] = 0.0f;

    for (int base = 0; base < cnt; base += 32) {
        int m = cnt - base; if (m > 32) m = 32;
        int es = 0;
        if (lane < m) es = g_esrc[start + base + lane];
        int passes = (m + 7) >> 3;
#pragma unroll 4
        for (int p = 0; p < 4; p++) {
            if (p >= passes) break;
            int idx = p * 8 + g4;
            int sj = __shfl_sync(0xffffffffu, es, idx);
            if (idx < m) {
                uint4 hv = hs4[(size_t)sj * 4 + l4];
                float2 f0 = __half22float2(*(half2*)&hv.x);
                float2 f1 = __half22float2(*(half2*)&hv.y);
                float2 f2 = __half22float2(*(half2*)&hv.z);
                float2 f3 = __half22float2(*(half2*)&hv.w);
                a[0] += f0.x; a[1] += f0.y; a[2] += f1.x; a[3] += f1.y;
                a[4] += f2.x; a[5] += f2.y; a[6] += f3.x; a[7] += f3.y;
            }
        }
    }

#pragma unroll
    for (int c = 0; c < 8; c++) {
        a[c] += __shfl_down_sync(0xffffffffu, a[c], 16);
        a[c] += __shfl_down_sync(0xffffffffu, a[c], 8);
        a[c] += __shfl_down_sync(0xffffffffu, a[c], 4);
    }

    if (lane < 4) {
        float4* p0 = (float4*)&g_agg[(size_t)node * NC + 8 * lane];
        float4 s0 = p0[0], s1 = p0[1];
        p0[0] = make_float4(s0.x + a[0], s0.y + a[1], s0.z + a[2], s0.w + a[3]);
        p0[1] = make_float4(s1.x + a[4], s1.y + a[5], s1.z + a[6], s1.w + a[7]);
    }
}

// ---------------------------------------------------------------- fixup (6)
__global__ void k_fix() {
    int n = g_ovfn;
    if (n > OVFCAP) n = OVFCAP;
    int lane = threadIdx.x & 31;
    int g  = lane >> 3;
    int l8 = lane & 7;
    const uint2* hs2 = (const uint2*)g_hs_h;
    int wid = (blockIdx.x * blockDim.x + threadIdx.x) >> 5;
    int nw  = (gridDim.x * blockDim.x) >> 5;
    for (int j = wid * 4 + g; j < n; j += nw * 4) {
        int2 e = g_ovf[j];
        uint2 hv = hs2[(size_t)e.x * 8 + l8];
        float2 fa = __half22float2(*(half2*)&hv.x);
        float2 fb = __half22float2(*(half2*)&hv.y);
        float* p = &g_agg[(size_t)e.y * NC + l8 * 4];
        asm volatile("red.global.add.v4.f32 [%0], {%1, %2, %3, %4};"
                     :: "l"(p), "f"(fa.x), "f"(fa.y), "f"(fb.x), "f"(fb.y)
                     : "memory");
    }
}

// ---------------------------------------------------------------- pooling (7)
__global__ void __launch_bounds__(256) k_pool(const int* __restrict__ batch) {
    __shared__ float sp[NG * NC];
    __shared__ float sc[NG];
    __shared__ int gmin, gmax;
    int tid = threadIdx.x;
    for (int i = tid; i < NG * NC; i += 256) sp[i] = 0.0f;
    if (tid < NG) sc[tid] = 0.0f;
    if (tid == 0) { gmin = NG; gmax = -1; }
    __syncthreads();

    int warp = tid >> 5, lane = tid & 31;
    int wid = blockIdx.x * 8 + warp;
    int nwarps = PBLK * 8;
    int per = (NN + nwarps - 1) / nwarps;
    int s0 = wid * per;
    int s1 = min(NN, s0 + per);

    float acc = 0.0f, cacc = 0.0f;
    int curg = -1, firstg = NG, lastg = -1;

    for (int i = s0; i < s1; i += 4) {
        int m = s1 - i; if (m > 4) m = 4;
        int   bb[4];
        float vv[4];
        float dd[4];
#pragma unroll
        for (int k = 0; k < 4; k++) {
            if (k < m) {
                bb[k] = __ldg(&batch[i + k]);
                vv[k] = g_agg[(size_t)(i + k) * NC + lane];
                dd[k] = (float)g_cur[i + k];
            }
        }
#pragma unroll
        for (int k = 0; k < 4; k++) {
            if (k < m) {
                if (bb[k] != curg) {
                    if (curg >= 0) {
                        atomicAdd(&sp[curg * NC + lane], acc);
                        if (lane == 0) atomicAdd(&sc[curg], cacc);
                    }
                    curg = bb[k]; acc = 0.0f; cacc = 0.0f;
                    if (curg < firstg) firstg = curg;
                    if (curg > lastg)  lastg = curg;
                }
                acc  += vv[k] * rsqrtf(dd[k] + 1.0f);
                cacc += 1.0f;
            }
        }
    }
    if (curg >= 0) {
        atomicAdd(&sp[curg * NC + lane], acc);
        if (lane == 0) atomicAdd(&sc[curg], cacc);
    }
    if (lane == 0 && lastg >= 0) {
        atomicMin(&gmin, firstg);
        atomicMax(&gmax, lastg);
    }
    __syncthreads();

    int lo = gmin, hi = gmax;
    if (hi >= lo) {
        for (int i = lo * NC + tid; i < (hi + 1) * NC; i += 256)
            atomicAdd(&g_pool[i], sp[i]);
        for (int g = lo + tid; g <= hi; g += 256)
            atomicAdd(&g_cnt[g], sc[g]);
    }
}

// ---------------------------------------------------------------- finalize (8)
__global__ void k_final(const float* __restrict__ b, float* __restrict__ out) {
    int i = blockIdx.x * blockDim.x + threadIdx.x;
    if (i < NG * NC) {
        int g = i >> 5, c = i & 31;
        float cnt = g_cnt[g];
        out[i] = (cnt > 0.0f) ? (g_pool[i] / cnt + b[c]) : 0.0f;
    }
}

// ---------------------------------------------------------------- launch
extern "C" void kernel_launch(void* const* d_in, const int* in_sizes, int n_in,
                              void* d_out, int out_size) {
    const float* x     = (const float*)d_in[0];
    const float* W     = (const float*)d_in[1];
    const float* b     = (const float*)d_in[2];
    const int*   ei    = (const int*)d_in[3];
    const int*   batch = (const int*)d_in[4];
    float*       out   = (float*)d_out;

    const int* src = ei;        // edge_index[0]
    const int* dst = ei + NE;   // edge_index[1]

    cudaFuncSetAttribute(k_gemm, cudaFuncAttributeMaxDynamicSharedMemorySize, GSMEM);

    k_zero <<<(NN + 255) / 256, 256>>>();
    k_build<<<(NE / 4 + 255) / 256, 256>>>(src, dst);
    k_zero2<<<(NG * NC + 255) / 256, 256>>>();
    k_gemm <<<(NN + GR - 1) / GR, 256, GSMEM>>>(x, W);     // slot 4 -> ncu
    k_gather<<<(NN + 7) / 8, 256>>>();
    k_fix  <<<16, 256>>>();
    k_pool <<<PBLK, 256>>>(batch);
    k_final<<<(NG * NC + 255) / 256, 256>>>(b, out);
}

// round 13
// speedup vs baseline: 1.6488x; 1.0588x over previous
#include <cuda_runtime.h>
#include <cuda_fp16.h>

#define NN 100000
#define NE 3200000
#define DIMK 256
#define NC 32
#define NG 64
#define CAP 96     // fixed CSR stride (deg ~ Poisson(32); P(>=96) ~ 1e-18)
#define OVFCAP 8192
#define PBLK 256   // pool blocks
#define GR 128     // rows per gemm block
#define RS 36      // stage row stride (floats): 144B, 16B-aligned, ldsm conflict-free
#define WFREG (2 * 8192)                   // W fragment floats (hi+lo)
#define GSMEM (WFREG * 4 + 2 * GR * RS * 4)  // 65536 + 36864 = 102400B

// Scratch (device globals; no allocation allowed)
__device__ int    g_cur[NN];                      // build cursor == final in-degree
__device__ int    g_esrc[(size_t)NN * CAP];       // fixed-stride CSR src lists
__device__ int2   g_ovf[OVFCAP];
__device__ int    g_ovfn;
__device__ __half g_hs_h[(size_t)NN * NC];        // h * dinv fp16 gather payload
__device__ float  g_agg[(size_t)NN * NC];         // self seed + edge sums (f32)
__device__ float  g_pool[NG * NC];
__device__ float  g_cnt[NG];

__device__ __forceinline__ unsigned tf32_bits(float v) {
    unsigned r;
    asm("cvt.rna.tf32.f32 %0, %1;" : "=r"(r) : "f"(v));
    return r;
}
__device__ __forceinline__ float to_tf32(float v) {
    return __uint_as_float(tf32_bits(v));
}
__device__ __forceinline__ void ldsm4(unsigned a[4], unsigned addr) {
    asm volatile("ldmatrix.sync.aligned.m8n8.x4.shared.b16 {%0,%1,%2,%3}, [%4];"
                 : "=r"(a[0]), "=r"(a[1]), "=r"(a[2]), "=r"(a[3]) : "r"(addr));
}
__device__ __forceinline__ void mma8(float c[4], const unsigned a[4],
                                     unsigned b0, unsigned b1) {
    asm volatile("mma.sync.aligned.m16n8k8.row.col.f32.tf32.tf32.f32 "
                 "{%0,%1,%2,%3}, {%4,%5,%6,%7}, {%8,%9}, {%0,%1,%2,%3};"
                 : "+f"(c[0]), "+f"(c[1]), "+f"(c[2]), "+f"(c[3])
                 : "r"(a[0]), "r"(a[1]), "r"(a[2]), "r"(a[3]), "r"(b0), "r"(b1));
}
__device__ __forceinline__ void cpasync16(unsigned dst, const void* src) {
    asm volatile("cp.async.cg.shared.global [%0], [%1], 16;"
                 :: "r"(dst), "l"(src) : "memory");
}

// ---------------------------------------------------------------- zero (1)
__global__ void k_zero() {
    int i = blockIdx.x * blockDim.x + threadIdx.x;
    if (i < NN) g_cur[i] = 0;
    if (i == 0) g_ovfn = 0;
}

// ---------------------------------------------------------------- CSR build (2)
__global__ void k_build(const int* __restrict__ src, const int* __restrict__ dst) {
    int i = blockIdx.x * blockDim.x + threadIdx.x;
    if (i * 4 < NE) {
        int4 s = ((const int4*)src)[i];
        int4 d = ((const int4*)dst)[i];
#pragma unroll
        for (int k = 0; k < 4; k++) {
            int dd = (k == 0) ? d.x : (k == 1) ? d.y : (k == 2) ? d.z : d.w;
            int ss = (k == 0) ? s.x : (k == 1) ? s.y : (k == 2) ? s.z : s.w;
            int p = atomicAdd(&g_cur[dd], 1);
            if (p < CAP) {
                g_esrc[(size_t)dd * CAP + p] = ss;
            } else {
                int q = atomicAdd(&g_ovfn, 1);
                if (q < OVFCAP) g_ovf[q] = make_int2(ss, dd);
            }
        }
    }
}

// ---------------------------------------------------------------- pad/zero2 (3)
__global__ void k_zero2() {
    int i = blockIdx.x * blockDim.x + threadIdx.x;
    if (i < NG * NC) g_pool[i] = 0.0f;
    if (i < NG) g_cnt[i] = 0.0f;
}

// ---------------------------------------------------------------- GEMM (4, ncu)
// tf32 mma.m16n8k8, 3-term hi/lo split. cp.async double-buffered raw-f32
// staging; ONE ldmatrix.x4 per kstep; split in registers. W frags in smem.
__global__ void __launch_bounds__(256) k_gemm(const float* __restrict__ x,
                                              const float* __restrict__ W) {
    extern __shared__ float sm[];
    float* wf = sm;                    // [2 ver][32 kstep][2 ntp][32 lane][4]
    float* st = sm + WFREG;            // 2 stage buffers [128][RS]

    int tid = threadIdx.x, w = tid >> 5, lane = tid & 31;
    int row0g = blockIdx.x * GR;
    unsigned stbase = (unsigned)__cvta_generic_to_shared(st);

    // One-time: pre-fragment W (hi & lo) in mma B-fragment order.
    for (int e = tid; e < 8192; e += 256) {
        int kstep = e >> 8;
        int rem   = e & 255;
        int ntp   = rem >> 7;
        int rem2  = rem & 127;
        int ln    = rem2 >> 2;
        int j     = rem2 & 3;
        int nt = ntp * 2 + (j >> 1);
        int b  = j & 1;
        int k  = kstep * 8 + (ln & 3) + b * 4;
        int n  = nt * 8 + (ln >> 2);
        float v  = W[k * NC + n];
        float hi = to_tf32(v);
        float lo = to_tf32(v - hi);
        int off = ((kstep * 2 + ntp) * 32 + ln) * 4 + j;
        wf[off]        = hi;
        wf[8192 + off] = lo;
    }

    // Stage chunk cc (32 k-floats) into buffer bsel via cp.async.
    auto stage = [&](int cc, int bsel) {
#pragma unroll
        for (int i = 0; i < 4; i++) {
            int f = tid + i * 256;           // granule 0..1023 (16B each)
            int row = f >> 3, q = f & 7;
            int rr = row0g + row; if (rr >= NN) rr = NN - 1;
            const float* src = x + (size_t)rr * DIMK + cc * 32 + q * 4;
            unsigned dst = stbase + (unsigned)((bsel * GR * RS + row * RS + q * 4) * 4);
            cpasync16(dst, src);
        }
        asm volatile("cp.async.commit_group;" ::: "memory");
    };

    float c[4][4];
#pragma unroll
    for (int nt = 0; nt < 4; nt++)
#pragma unroll
        for (int q = 0; q < 4; q++) c[nt][q] = 0.0f;

    stage(0, 0);
    __syncthreads();   // W preamble + first-stage visibility ordering

    for (int cc = 0; cc < 8; cc++) {
        if (cc < 7) stage(cc + 1, (cc + 1) & 1);
        if (cc < 7) asm volatile("cp.async.wait_group 1;" ::: "memory");
        else        asm volatile("cp.async.wait_group 0;" ::: "memory");
        __syncthreads();

        const float* buf = st + (cc & 1) * GR * RS;
#pragma unroll
        for (int ks = 0; ks < 4; ks++) {
            int kstep = cc * 4 + ks;
            int soff = (w * 16 + (lane & 15)) * RS + ks * 8 + (lane >> 4) * 4;
            unsigned araw[4];
            ldsm4(araw, (unsigned)__cvta_generic_to_shared(buf + soff));
            unsigned ah[4], al[4];
#pragma unroll
            for (int i = 0; i < 4; i++) {
                float v = __uint_as_float(araw[i]);
                float h = to_tf32(v);
                ah[i] = __float_as_uint(h);
                al[i] = tf32_bits(v - h);
            }
#pragma unroll
            for (int ntp = 0; ntp < 2; ntp++) {
                int boff = ((kstep * 2 + ntp) * 32 + lane) * 4;
                uint4 wh = *(uint4*)&wf[boff];
                uint4 wl = *(uint4*)&wf[8192 + boff];
                mma8(c[2 * ntp],     ah, wh.x, wh.y);
                mma8(c[2 * ntp],     ah, wl.x, wl.y);
                mma8(c[2 * ntp],     al, wh.x, wh.y);
                mma8(c[2 * ntp + 1], ah, wh.z, wh.w);
                mma8(c[2 * ntp + 1], ah, wl.z, wl.w);
                mma8(c[2 * ntp + 1], al, wh.z, wh.w);
            }
        }
        __syncthreads();   // free this buffer for the next-next stage
    }

    // Epilogue: c0,c1 -> row g; c2,c3 -> row g+8; cols nt*8 + 2t,2t+1
    int g = lane >> 2, t = lane & 3;
#pragma unroll
    for (int rh = 0; rh < 2; rh++) {
        int row = row0g + w * 16 + g + rh * 8;
        if (row < NN) {
            float di = rsqrtf((float)g_cur[row] + 1.0f);
#pragma unroll
            for (int nt = 0; nt < 4; nt++) {
                float v0 = c[nt][rh * 2 + 0] * di;
                float v1 = c[nt][rh * 2 + 1] * di;
                int col = nt * 8 + 2 * t;
                *(float2*)&g_agg[(size_t)row * NC + col] = make_float2(v0, v1);
                half2 hp = __floats2half2_rn(v0, v1);
                *(unsigned*)&g_hs_h[(size_t)row * NC + col] = *(unsigned*)&hp;
            }
        }
    }
}

// ---------------------------------------------------------------- gather (5)
__global__ void __launch_bounds__(256) k_gather() {
    int node = (blockIdx.x * blockDim.x + threadIdx.x) >> 5;
    if (node >= NN) return;
    int lane = threadIdx.x & 31;
    int g4 = lane >> 2;
    int l4 = lane & 3;

    size_t start = (size_t)node * CAP;
    int cnt = g_cur[node];
    if (cnt > CAP) cnt = CAP;

    const uint4* hs4 = (const uint4*)g_hs_h;
    float a[8];
#pragma unroll
    for (int c = 0; c < 8; c++) a[c] = 0.0f;

    for (int base = 0; base < cnt; base += 32) {
        int m = cnt - base; if (m > 32) m = 32;
        int es = 0;
        if (lane < m) es = g_esrc[start + base + lane];
        int passes = (m + 7) >> 3;
#pragma unroll 4
        for (int p = 0; p < 4; p++) {
            if (p >= passes) break;
            int idx = p * 8 + g4;
            int sj = __shfl_sync(0xffffffffu, es, idx);
            if (idx < m) {
                uint4 hv = hs4[(size_t)sj * 4 + l4];
                float2 f0 = __half22float2(*(half2*)&hv.x);
                float2 f1 = __half22float2(*(half2*)&hv.y);
                float2 f2 = __half22float2(*(half2*)&hv.z);
                float2 f3 = __half22float2(*(half2*)&hv.w);
                a[0] += f0.x; a[1] += f0.y; a[2] += f1.x; a[3] += f1.y;
                a[4] += f2.x; a[5] += f2.y; a[6] += f3.x; a[7] += f3.y;
            }
        }
    }

#pragma unroll
    for (int c = 0; c < 8; c++) {
        a[c] += __shfl_down_sync(0xffffffffu, a[c], 16);
        a[c] += __shfl_down_sync(0xffffffffu, a[c], 8);
        a[c] += __shfl_down_sync(0xffffffffu, a[c], 4);
    }

    if (lane < 4) {
        float4* p0 = (float4*)&g_agg[(size_t)node * NC + 8 * lane];
        float4 s0 = p0[0], s1 = p0[1];
        p0[0] = make_float4(s0.x + a[0], s0.y + a[1], s0.z + a[2], s0.w + a[3]);
        p0[1] = make_float4(s1.x + a[4], s1.y + a[5], s1.z + a[6], s1.w + a[7]);
    }
}

// ---------------------------------------------------------------- fixup (6)
__global__ void k_fix() {
    int n = g_ovfn;
    if (n > OVFCAP) n = OVFCAP;
    int lane = threadIdx.x & 31;
    int g  = lane >> 3;
    int l8 = lane & 7;
    const uint2* hs2 = (const uint2*)g_hs_h;
    int wid = (blockIdx.x * blockDim.x + threadIdx.x) >> 5;
    int nw  = (gridDim.x * blockDim.x) >> 5;
    for (int j = wid * 4 + g; j < n; j += nw * 4) {
        int2 e = g_ovf[j];
        uint2 hv = hs2[(size_t)e.x * 8 + l8];
        float2 fa = __half22float2(*(half2*)&hv.x);
        float2 fb = __half22float2(*(half2*)&hv.y);
        float* p = &g_agg[(size_t)e.y * NC + l8 * 4];
        asm volatile("red.global.add.v4.f32 [%0], {%1, %2, %3, %4};"
                     :: "l"(p), "f"(fa.x), "f"(fa.y), "f"(fb.x), "f"(fb.y)
                     : "memory");
    }
}

// ---------------------------------------------------------------- pooling (7)
__global__ void __launch_bounds__(256) k_pool(const int* __restrict__ batch) {
    __shared__ float sp[NG * NC];
    __shared__ float sc[NG];
    __shared__ int gmin, gmax;
    int tid = threadIdx.x;
    for (int i = tid; i < NG * NC; i += 256) sp[i] = 0.0f;
    if (tid < NG) sc[tid] = 0.0f;
    if (tid == 0) { gmin = NG; gmax = -1; }
    __syncthreads();

    int warp = tid >> 5, lane = tid & 31;
    int wid = blockIdx.x * 8 + warp;
    int nwarps = PBLK * 8;
    int per = (NN + nwarps - 1) / nwarps;
    int s0 = wid * per;
    int s1 = min(NN, s0 + per);

    float acc = 0.0f, cacc = 0.0f;
    int curg = -1, firstg = NG, lastg = -1;

    for (int i = s0; i < s1; i += 4) {
        int m = s1 - i; if (m > 4) m = 4;
        int   bb[4];
        float vv[4];
        float dd[4];
#pragma unroll
        for (int k = 0; k < 4; k++) {
            if (k < m) {
                bb[k] = __ldg(&batch[i + k]);
                vv[k] = g_agg[(size_t)(i + k) * NC + lane];
                dd[k] = (float)g_cur[i + k];
            }
        }
#pragma unroll
        for (int k = 0; k < 4; k++) {
            if (k < m) {
                if (bb[k] != curg) {
                    if (curg >= 0) {
                        atomicAdd(&sp[curg * NC + lane], acc);
                        if (lane == 0) atomicAdd(&sc[curg], cacc);
                    }
                    curg = bb[k]; acc = 0.0f; cacc = 0.0f;
                    if (curg < firstg) firstg = curg;
                    if (curg > lastg)  lastg = curg;
                }
                acc  += vv[k] * rsqrtf(dd[k] + 1.0f);
                cacc += 1.0f;
            }
        }
    }
    if (curg >= 0) {
        atomicAdd(&sp[curg * NC + lane], acc);
        if (lane == 0) atomicAdd(&sc[curg], cacc);
    }
    if (lane == 0 && lastg >= 0) {
        atomicMin(&gmin, firstg);
        atomicMax(&gmax, lastg);
    }
    __syncthreads();

    int lo = gmin, hi = gmax;
    if (hi >= lo) {
        for (int i = lo * NC + tid; i < (hi + 1) * NC; i += 256)
            atomicAdd(&g_pool[i], sp[i]);
        for (int g = lo + tid; g <= hi; g += 256)
            atomicAdd(&g_cnt[g], sc[g]);
    }
}

// ---------------------------------------------------------------- finalize (8)
__global__ void k_final(const float* __restrict__ b, float* __restrict__ out) {
    int i = blockIdx.x * blockDim.x + threadIdx.x;
    if (i < NG * NC) {
        int g = i >> 5, c = i & 31;
        float cnt = g_cnt[g];
        out[i] = (cnt > 0.0f) ? (g_pool[i] / cnt + b[c]) : 0.0f;
    }
}

// ---------------------------------------------------------------- launch
extern "C" void kernel_launch(void* const* d_in, const int* in_sizes, int n_in,
                              void* d_out, int out_size) {
    const float* x     = (const float*)d_in[0];
    const float* W     = (const float*)d_in[1];
    const float* b     = (const float*)d_in[2];
    const int*   ei    = (const int*)d_in[3];
    const int*   batch = (const int*)d_in[4];
    float*       out   = (float*)d_out;

    const int* src = ei;        // edge_index[0]
    const int* dst = ei + NE;   // edge_index[1]

    cudaFuncSetAttribute(k_gemm, cudaFuncAttributeMaxDynamicSharedMemorySize, GSMEM);

    k_zero <<<(NN + 255) / 256, 256>>>();
    k_build<<<(NE / 4 + 255) / 256, 256>>>(src, dst);
    k_zero2<<<(NG * NC + 255) / 256, 256>>>();
    k_gemm <<<(NN + GR - 1) / GR, 256, GSMEM>>>(x, W);     // slot 4 -> ncu
    k_gather<<<(NN + 7) / 8, 256>>>();
    k_fix  <<<16, 256>>>();
    k_pool <<<PBLK, 256>>>(batch);
    k_final<<<(NG * NC + 255) / 256, 256>>>(b, out);
}

// round 14
// speedup vs baseline: 1.7432x; 1.0572x over previous
#include <cuda_runtime.h>
#include <cuda_fp16.h>

#define NN 100000
#define NE 3200000
#define DIMK 256
#define NC 32
#define NG 64
#define CAP 96     // fixed CSR stride (deg ~ Poisson(32); P(>=96) ~ 1e-18)
#define OVFCAP 8192
#define PBLK 256   // pool blocks
#define GR 128     // rows per gemm block
#define RS 36      // stage row stride (floats): 144B, 16B-aligned, ldsm conflict-free
#define GSMEM (2 * GR * RS * 4)   // stages only: 36864B -> 4 blocks/SM

// Scratch (device globals; no allocation allowed)
__device__ int    g_cur[NN];                      // build cursor == final in-degree
__device__ int    g_esrc[(size_t)NN * CAP];       // fixed-stride CSR src lists
__device__ int2   g_ovf[OVFCAP];
__device__ int    g_ovfn;
__device__ __half g_hs_h[(size_t)NN * NC];        // h * dinv fp16 gather payload
__device__ float  g_agg[(size_t)NN * NC];         // self seed + edge sums (f32)
__device__ float  g_pool[NG * NC];
__device__ float  g_cnt[NG];
__device__ float4 g_wf4[4096];                    // W frags: [hi|lo][kstep][ntp][lane]

__device__ __forceinline__ unsigned tf32_bits(float v) {
    unsigned r;
    asm("cvt.rna.tf32.f32 %0, %1;" : "=r"(r) : "f"(v));
    return r;
}
__device__ __forceinline__ float to_tf32(float v) {
    return __uint_as_float(tf32_bits(v));
}
__device__ __forceinline__ void ldsm4(unsigned a[4], unsigned addr) {
    asm volatile("ldmatrix.sync.aligned.m8n8.x4.shared.b16 {%0,%1,%2,%3}, [%4];"
                 : "=r"(a[0]), "=r"(a[1]), "=r"(a[2]), "=r"(a[3]) : "r"(addr));
}
__device__ __forceinline__ void mma8(float c[4], const unsigned a[4],
                                     unsigned b0, unsigned b1) {
    asm volatile("mma.sync.aligned.m16n8k8.row.col.f32.tf32.tf32.f32 "
                 "{%0,%1,%2,%3}, {%4,%5,%6,%7}, {%8,%9}, {%0,%1,%2,%3};"
                 : "+f"(c[0]), "+f"(c[1]), "+f"(c[2]), "+f"(c[3])
                 : "r"(a[0]), "r"(a[1]), "r"(a[2]), "r"(a[3]), "r"(b0), "r"(b1));
}
__device__ __forceinline__ void cpasync16(unsigned dst, const void* src) {
    asm volatile("cp.async.cg.shared.global [%0], [%1], 16;"
                 :: "r"(dst), "l"(src) : "memory");
}

// ---------------------------------------------------------------- zero (1)
__global__ void k_zero() {
    int i = blockIdx.x * blockDim.x + threadIdx.x;
    if (i < NN) g_cur[i] = 0;
    if (i == 0) g_ovfn = 0;
}

// ---------------------------------------------------------------- CSR build (2)
__global__ void k_build(const int* __restrict__ src, const int* __restrict__ dst) {
    int i = blockIdx.x * blockDim.x + threadIdx.x;
    if (i * 4 < NE) {
        int4 s = ((const int4*)src)[i];
        int4 d = ((const int4*)dst)[i];
#pragma unroll
        for (int k = 0; k < 4; k++) {
            int dd = (k == 0) ? d.x : (k == 1) ? d.y : (k == 2) ? d.z : d.w;
            int ss = (k == 0) ? s.x : (k == 1) ? s.y : (k == 2) ? s.z : s.w;
            int p = atomicAdd(&g_cur[dd], 1);
            if (p < CAP) {
                g_esrc[(size_t)dd * CAP + p] = ss;
            } else {
                int q = atomicAdd(&g_ovfn, 1);
                if (q < OVFCAP) g_ovf[q] = make_int2(ss, dd);
            }
        }
    }
}

// ---------------------------------------------------------------- prep (3)
// Zero pool bins AND compute W fragments ONCE (shared by all gemm blocks).
__global__ void k_prep(const float* __restrict__ W) {
    int i = blockIdx.x * blockDim.x + threadIdx.x;   // 0..8191
    if (i < NG * NC) g_pool[i] = 0.0f;
    if (i < NG) g_cnt[i] = 0.0f;
    if (i < 8192) {
        int kstep = i >> 8;
        int rem   = i & 255;
        int ntp   = rem >> 7;
        int rem2  = rem & 127;
        int ln    = rem2 >> 2;
        int j     = rem2 & 3;
        int nt = ntp * 2 + (j >> 1);
        int b  = j & 1;
        int k  = kstep * 8 + (ln & 3) + b * 4;
        int n  = nt * 8 + (ln >> 2);
        float v  = W[k * NC + n];
        float hi = to_tf32(v);
        float lo = to_tf32(v - hi);
        int slot = (kstep * 2 + ntp) * 32 + ln;      // 0..2047
        ((float*)&g_wf4[slot])[j]        = hi;
        ((float*)&g_wf4[2048 + slot])[j] = lo;
    }
}

// ---------------------------------------------------------------- GEMM (4, ncu)
// tf32 mma.m16n8k8, 3-term hi/lo split. cp.async double-buffered raw-f32
// staging; ONE ldmatrix.x4 per kstep; W frags from L1-resident global.
__global__ void __launch_bounds__(256) k_gemm(const float* __restrict__ x) {
    extern __shared__ float st[];      // 2 stage buffers [128][RS]

    int tid = threadIdx.x, w = tid >> 5, lane = tid & 31;
    int row0g = blockIdx.x * GR;
    unsigned stbase = (unsigned)__cvta_generic_to_shared(st);

    // Stage chunk cc (32 k-floats) into buffer bsel via cp.async.
    auto stage = [&](int cc, int bsel) {
#pragma unroll
        for (int i = 0; i < 4; i++) {
            int f = tid + i * 256;           // granule 0..1023 (16B each)
            int row = f >> 3, q = f & 7;
            int rr = row0g + row; if (rr >= NN) rr = NN - 1;
            const float* src = x + (size_t)rr * DIMK + cc * 32 + q * 4;
            unsigned dst = stbase + (unsigned)((bsel * GR * RS + row * RS + q * 4) * 4);
            cpasync16(dst, src);
        }
        asm volatile("cp.async.commit_group;" ::: "memory");
    };

    float c[4][4];
#pragma unroll
    for (int nt = 0; nt < 4; nt++)
#pragma unroll
        for (int q = 0; q < 4; q++) c[nt][q] = 0.0f;

    stage(0, 0);

    for (int cc = 0; cc < 8; cc++) {
        if (cc < 7) stage(cc + 1, (cc + 1) & 1);
        if (cc < 7) asm volatile("cp.async.wait_group 1;" ::: "memory");
        else        asm volatile("cp.async.wait_group 0;" ::: "memory");
        __syncthreads();

        const float* buf = st + (cc & 1) * GR * RS;
#pragma unroll
        for (int ks = 0; ks < 4; ks++) {
            int kstep = cc * 4 + ks;
            int soff = (w * 16 + (lane & 15)) * RS + ks * 8 + (lane >> 4) * 4;
            unsigned araw[4];
            ldsm4(araw, (unsigned)__cvta_generic_to_shared(buf + soff));
            unsigned ah[4], al[4];
#pragma unroll
            for (int i = 0; i < 4; i++) {
                float v = __uint_as_float(araw[i]);
                float h = to_tf32(v);
                ah[i] = __float_as_uint(h);
                al[i] = tf32_bits(v - h);
            }
#pragma unroll
            for (int ntp = 0; ntp < 2; ntp++) {
                int slot = (kstep * 2 + ntp) * 32 + lane;
                float4 whf = __ldg(&g_wf4[slot]);
                float4 wlf = __ldg(&g_wf4[2048 + slot]);
                uint4 wh = *(uint4*)&whf;
                uint4 wl = *(uint4*)&wlf;
                mma8(c[2 * ntp],     ah, wh.x, wh.y);
                mma8(c[2 * ntp],     ah, wl.x, wl.y);
                mma8(c[2 * ntp],     al, wh.x, wh.y);
                mma8(c[2 * ntp + 1], ah, wh.z, wh.w);
                mma8(c[2 * ntp + 1], ah, wl.z, wl.w);
                mma8(c[2 * ntp + 1], al, wh.z, wh.w);
            }
        }
        __syncthreads();   // free this buffer for the next-next stage
    }

    // Epilogue: c0,c1 -> row g; c2,c3 -> row g+8; cols nt*8 + 2t,2t+1
    int g = lane >> 2, t = lane & 3;
#pragma unroll
    for (int rh = 0; rh < 2; rh++) {
        int row = row0g + w * 16 + g + rh * 8;
        if (row < NN) {
            float di = rsqrtf((float)g_cur[row] + 1.0f);
#pragma unroll
            for (int nt = 0; nt < 4; nt++) {
                float v0 = c[nt][rh * 2 + 0] * di;
                float v1 = c[nt][rh * 2 + 1] * di;
                int col = nt * 8 + 2 * t;
                *(float2*)&g_agg[(size_t)row * NC + col] = make_float2(v0, v1);
                half2 hp = __floats2half2_rn(v0, v1);
                *(unsigned*)&g_hs_h[(size_t)row * NC + col] = *(unsigned*)&hp;
            }
        }
    }
}

// ---------------------------------------------------------------- gather (5)
__global__ void __launch_bounds__(256) k_gather() {
    int node = (blockIdx.x * blockDim.x + threadIdx.x) >> 5;
    if (node >= NN) return;
    int lane = threadIdx.x & 31;
    int g4 = lane >> 2;
    int l4 = lane & 3;

    size_t start = (size_t)node * CAP;
    int cnt = g_cur[node];
    if (cnt > CAP) cnt = CAP;

    const uint4* hs4 = (const uint4*)g_hs_h;
    float a[8];
#pragma unroll
    for (int c = 0; c < 8; c++) a[c] = 0.0f;

    for (int base = 0; base < cnt; base += 32) {
        int m = cnt - base; if (m > 32) m = 32;
        int es = 0;
        if (lane < m) es = g_esrc[start + base + lane];
        int passes = (m + 7) >> 3;
#pragma unroll 4
        for (int p = 0; p < 4; p++) {
            if (p >= passes) break;
            int idx = p * 8 + g4;
            int sj = __shfl_sync(0xffffffffu, es, idx);
            if (idx < m) {
                uint4 hv = hs4[(size_t)sj * 4 + l4];
                float2 f0 = __half22float2(*(half2*)&hv.x);
                float2 f1 = __half22float2(*(half2*)&hv.y);
                float2 f2 = __half22float2(*(half2*)&hv.z);
                float2 f3 = __half22float2(*(half2*)&hv.w);
                a[0] += f0.x; a[1] += f0.y; a[2] += f1.x; a[3] += f1.y;
                a[4] += f2.x; a[5] += f2.y; a[6] += f3.x; a[7] += f3.y;
            }
        }
    }

#pragma unroll
    for (int c = 0; c < 8; c++) {
        a[c] += __shfl_down_sync(0xffffffffu, a[c], 16);
        a[c] += __shfl_down_sync(0xffffffffu, a[c], 8);
        a[c] += __shfl_down_sync(0xffffffffu, a[c], 4);
    }

    if (lane < 4) {
        float4* p0 = (float4*)&g_agg[(size_t)node * NC + 8 * lane];
        float4 s0 = p0[0], s1 = p0[1];
        p0[0] = make_float4(s0.x + a[0], s0.y + a[1], s0.z + a[2], s0.w + a[3]);
        p0[1] = make_float4(s1.x + a[4], s1.y + a[5], s1.z + a[6], s1.w + a[7]);
    }
}

// ---------------------------------------------------------------- fixup (6)
__global__ void k_fix() {
    int n = g_ovfn;
    if (n > OVFCAP) n = OVFCAP;
    int lane = threadIdx.x & 31;
    int g  = lane >> 3;
    int l8 = lane & 7;
    const uint2* hs2 = (const uint2*)g_hs_h;
    int wid = (blockIdx.x * blockDim.x + threadIdx.x) >> 5;
    int nw  = (gridDim.x * blockDim.x) >> 5;
    for (int j = wid * 4 + g; j < n; j += nw * 4) {
        int2 e = g_ovf[j];
        uint2 hv = hs2[(size_t)e.x * 8 + l8];
        float2 fa = __half22float2(*(half2*)&hv.x);
        float2 fb = __half22float2(*(half2*)&hv.y);
        float* p = &g_agg[(size_t)e.y * NC + l8 * 4];
        asm volatile("red.global.add.v4.f32 [%0], {%1, %2, %3, %4};"
                     :: "l"(p), "f"(fa.x), "f"(fa.y), "f"(fb.x), "f"(fb.y)
                     : "memory");
    }
}

// ---------------------------------------------------------------- pooling (7)
__global__ void __launch_bounds__(256) k_pool(const int* __restrict__ batch) {
    __shared__ float sp[NG * NC];
    __shared__ float sc[NG];
    __shared__ int gmin, gmax;
    int tid = threadIdx.x;
    for (int i = tid; i < NG * NC; i += 256) sp[i] = 0.0f;
    if (tid < NG) sc[tid] = 0.0f;
    if (tid == 0) { gmin = NG; gmax = -1; }
    __syncthreads();

    int warp = tid >> 5, lane = tid & 31;
    int wid = blockIdx.x * 8 + warp;
    int nwarps = PBLK * 8;
    int per = (NN + nwarps - 1) / nwarps;
    int s0 = wid * per;
    int s1 = min(NN, s0 + per);

    float acc = 0.0f, cacc = 0.0f;
    int curg = -1, firstg = NG, lastg = -1;

    for (int i = s0; i < s1; i += 4) {
        int m = s1 - i; if (m > 4) m = 4;
        int   bb[4];
        float vv[4];
        float dd[4];
#pragma unroll
        for (int k = 0; k < 4; k++) {
            if (k < m) {
                bb[k] = __ldg(&batch[i + k]);
                vv[k] = g_agg[(size_t)(i + k) * NC + lane];
                dd[k] = (float)g_cur[i + k];
            }
        }
#pragma unroll
        for (int k = 0; k < 4; k++) {
            if (k < m) {
                if (bb[k] != curg) {
                    if (curg >= 0) {
                        atomicAdd(&sp[curg * NC + lane], acc);
                        if (lane == 0) atomicAdd(&sc[curg], cacc);
                    }
                    curg = bb[k]; acc = 0.0f; cacc = 0.0f;
                    if (curg < firstg) firstg = curg;
                    if (curg > lastg)  lastg = curg;
                }
                acc  += vv[k] * rsqrtf(dd[k] + 1.0f);
                cacc += 1.0f;
            }
        }
    }
    if (curg >= 0) {
        atomicAdd(&sp[curg * NC + lane], acc);
        if (lane == 0) atomicAdd(&sc[curg], cacc);
    }
    if (lane == 0 && lastg >= 0) {
        atomicMin(&gmin, firstg);
        atomicMax(&gmax, lastg);
    }
    __syncthreads();

    int lo = gmin, hi = gmax;
    if (hi >= lo) {
        for (int i = lo * NC + tid; i < (hi + 1) * NC; i += 256)
            atomicAdd(&g_pool[i], sp[i]);
        for (int g = lo + tid; g <= hi; g += 256)
            atomicAdd(&g_cnt[g], sc[g]);
    }
}

// ---------------------------------------------------------------- finalize (8)
__global__ void k_final(const float* __restrict__ b, float* __restrict__ out) {
    int i = blockIdx.x * blockDim.x + threadIdx.x;
    if (i < NG * NC) {
        int g = i >> 5, c = i & 31;
        float cnt = g_cnt[g];
        out[i] = (cnt > 0.0f) ? (g_pool[i] / cnt + b[c]) : 0.0f;
    }
}

// ---------------------------------------------------------------- launch
extern "C" void kernel_launch(void* const* d_in, const int* in_sizes, int n_in,
                              void* d_out, int out_size) {
    const float* x     = (const float*)d_in[0];
    const float* W     = (const float*)d_in[1];
    const float* b     = (const float*)d_in[2];
    const int*   ei    = (const int*)d_in[3];
    const int*   batch = (const int*)d_in[4];
    float*       out   = (float*)d_out;

    const int* src = ei;        // edge_index[0]
    const int* dst = ei + NE;   // edge_index[1]

    k_zero <<<(NN + 255) / 256, 256>>>();
    k_build<<<(NE / 4 + 255) / 256, 256>>>(src, dst);
    k_prep <<<32, 256>>>(W);
    k_gemm <<<(NN + GR - 1) / GR, 256, GSMEM>>>(x);        // slot 4 -> ncu
    k_gather<<<(NN + 7) / 8, 256>>>();
    k_fix  <<<16, 256>>>();
    k_pool <<<PBLK, 256>>>(batch);
    k_final<<<(NG * NC + 255) / 256, 256>>>(b, out);
}

// round 15
// speedup vs baseline: 1.8631x; 1.0688x over previous
#include <cuda_runtime.h>
#include <cuda_fp16.h>

#define NN 100000
#define NE 3200000
#define DIMK 256
#define NC 32
#define NG 64
#define CAP 96     // fixed CSR stride (deg ~ Poisson(32); P(>=96) ~ 1e-18)
#define OVFCAP 8192
#define PBLK 256   // pool blocks
#define GR 128     // rows per gemm block
#define RS 36      // stage row stride (floats): 144B, ldsm conflict-free
#define NGEMM ((NN + GR - 1) / GR)      // 782 gemm-role blocks
#define NBUILD ((NE / 4 + 255) / 256)   // 3125 build-role blocks

// Scratch (device globals; no allocation allowed)
__device__ int    g_cur[NN];                      // build cursor == final in-degree
__device__ int    g_esrc[(size_t)NN * CAP];       // fixed-stride CSR src lists
__device__ int2   g_ovf[OVFCAP];
__device__ int    g_ovfn;
__device__ __half g_hs_h[(size_t)NN * NC];        // h * dinv fp16 gather payload
__device__ float  g_agg[(size_t)NN * NC];         // raw h -> hs seed + edge sums
__device__ float  g_pool[NG * NC];
__device__ float  g_cnt[NG];
__device__ float4 g_wf4[4096];                    // W frags: [hi|lo][kstep][ntp][lane]

__device__ __forceinline__ unsigned tf32_bits(float v) {
    unsigned r;
    asm("cvt.rna.tf32.f32 %0, %1;" : "=r"(r) : "f"(v));
    return r;
}
__device__ __forceinline__ float to_tf32(float v) {
    return __uint_as_float(tf32_bits(v));
}
__device__ __forceinline__ void ldsm4(unsigned a[4], unsigned addr) {
    asm volatile("ldmatrix.sync.aligned.m8n8.x4.shared.b16 {%0,%1,%2,%3}, [%4];"
                 : "=r"(a[0]), "=r"(a[1]), "=r"(a[2]), "=r"(a[3]) : "r"(addr));
}
__device__ __forceinline__ void mma8(float c[4], const unsigned a[4],
                                     unsigned b0, unsigned b1) {
    asm volatile("mma.sync.aligned.m16n8k8.row.col.f32.tf32.tf32.f32 "
                 "{%0,%1,%2,%3}, {%4,%5,%6,%7}, {%8,%9}, {%0,%1,%2,%3};"
                 : "+f"(c[0]), "+f"(c[1]), "+f"(c[2]), "+f"(c[3])
                 : "r"(a[0]), "r"(a[1]), "r"(a[2]), "r"(a[3]), "r"(b0), "r"(b1));
}
__device__ __forceinline__ void cpasync16(unsigned dst, const void* src) {
    asm volatile("cp.async.cg.shared.global [%0], [%1], 16;"
                 :: "r"(dst), "l"(src) : "memory");
}

// ---------------------------------------------------------------- zero (1)
__global__ void k_zero() {
    int i = blockIdx.x * blockDim.x + threadIdx.x;
    if (i < NN) g_cur[i] = 0;
    if (i == 0) g_ovfn = 0;
}

// ---------------------------------------------------------------- prep (2)
// Zero pool bins AND compute W fragments ONCE.
__global__ void k_prep(const float* __restrict__ W) {
    int i = blockIdx.x * blockDim.x + threadIdx.x;   // 0..8191
    if (i < NG * NC) g_pool[i] = 0.0f;
    if (i < NG) g_cnt[i] = 0.0f;
    if (i < 8192) {
        int kstep = i >> 8;
        int rem   = i & 255;
        int ntp   = rem >> 7;
        int rem2  = rem & 127;
        int ln    = rem2 >> 2;
        int j     = rem2 & 3;
        int nt = ntp * 2 + (j >> 1);
        int b  = j & 1;
        int k  = kstep * 8 + (ln & 3) + b * 4;
        int n  = nt * 8 + (ln >> 2);
        float v  = W[k * NC + n];
        float hi = to_tf32(v);
        float lo = to_tf32(v - hi);
        int slot = (kstep * 2 + ntp) * 32 + ln;      // 0..2047
        ((float*)&g_wf4[slot])[j]        = hi;
        ((float*)&g_wf4[2048 + slot])[j] = lo;
    }
}

// ---------------------------------------------------------------- pad (3)
__global__ void k_pad() {
    if (threadIdx.x == 0 && blockIdx.x == 0) g_ovfn = 0;
}

// ---------------------------------------------------------------- fused (4, ncu)
// Role-split: bid%5==0 -> tf32 MMA gemm (writes RAW h, no deg dependency);
// else -> CSR build. Independent work overlaps tensor/DRAM with L2-atomics.
__global__ void __launch_bounds__(256) k_fused(const int* __restrict__ src,
                                               const int* __restrict__ dst,
                                               const float* __restrict__ x) {
    __shared__ float st[2 * GR * RS];   // 36864B static (gemm role only)

    int bid = blockIdx.x;
    int tid = threadIdx.x;

    if (bid % 5 != 0) {
        // ---- build role ----
        int build_id = bid - bid / 5 - 1;
        if (build_id >= NBUILD) return;
        int i = build_id * 256 + tid;
        if (i * 4 < NE) {
            int4 s = ((const int4*)src)[i];
            int4 d = ((const int4*)dst)[i];
#pragma unroll
            for (int k = 0; k < 4; k++) {
                int dd = (k == 0) ? d.x : (k == 1) ? d.y : (k == 2) ? d.z : d.w;
                int ss = (k == 0) ? s.x : (k == 1) ? s.y : (k == 2) ? s.z : s.w;
                int p = atomicAdd(&g_cur[dd], 1);
                if (p < CAP) {
                    g_esrc[(size_t)dd * CAP + p] = ss;
                } else {
                    int q = atomicAdd(&g_ovfn, 1);
                    if (q < OVFCAP) g_ovf[q] = make_int2(ss, dd);
                }
            }
        }
        return;
    }

    // ---- gemm role ----
    int gb = bid / 5;                  // 0..781
    int w = tid >> 5, lane = tid & 31;
    int row0g = gb * GR;
    unsigned stbase = (unsigned)__cvta_generic_to_shared(st);

    auto stage = [&](int cc, int bsel) {
#pragma unroll
        for (int i = 0; i < 4; i++) {
            int f = tid + i * 256;           // granule 0..1023 (16B each)
            int row = f >> 3, q = f & 7;
            int rr = row0g + row; if (rr >= NN) rr = NN - 1;
            const float* srcp = x + (size_t)rr * DIMK + cc * 32 + q * 4;
            unsigned dstp = stbase + (unsigned)((bsel * GR * RS + row * RS + q * 4) * 4);
            cpasync16(dstp, srcp);
        }
        asm volatile("cp.async.commit_group;" ::: "memory");
    };

    float c[4][4];
#pragma unroll
    for (int nt = 0; nt < 4; nt++)
#pragma unroll
        for (int q = 0; q < 4; q++) c[nt][q] = 0.0f;

    stage(0, 0);

    for (int cc = 0; cc < 8; cc++) {
        if (cc < 7) stage(cc + 1, (cc + 1) & 1);
        if (cc < 7) asm volatile("cp.async.wait_group 1;" ::: "memory");
        else        asm volatile("cp.async.wait_group 0;" ::: "memory");
        __syncthreads();

        const float* buf = st + (cc & 1) * GR * RS;
#pragma unroll
        for (int ks = 0; ks < 4; ks++) {
            int kstep = cc * 4 + ks;
            int soff = (w * 16 + (lane & 15)) * RS + ks * 8 + (lane >> 4) * 4;
            unsigned araw[4];
            ldsm4(araw, (unsigned)__cvta_generic_to_shared(buf + soff));
            unsigned ah[4], al[4];
#pragma unroll
            for (int i = 0; i < 4; i++) {
                float v = __uint_as_float(araw[i]);
                float h = to_tf32(v);
                ah[i] = __float_as_uint(h);
                al[i] = tf32_bits(v - h);
            }
#pragma unroll
            for (int ntp = 0; ntp < 2; ntp++) {
                int slot = (kstep * 2 + ntp) * 32 + lane;
                float4 whf = __ldg(&g_wf4[slot]);
                float4 wlf = __ldg(&g_wf4[2048 + slot]);
                uint4 wh = *(uint4*)&whf;
                uint4 wl = *(uint4*)&wlf;
                mma8(c[2 * ntp],     ah, wh.x, wh.y);
                mma8(c[2 * ntp],     ah, wl.x, wl.y);
                mma8(c[2 * ntp],     al, wh.x, wh.y);
                mma8(c[2 * ntp + 1], ah, wh.z, wh.w);
                mma8(c[2 * ntp + 1], ah, wl.z, wl.w);
                mma8(c[2 * ntp + 1], al, wh.z, wh.w);
            }
        }
        __syncthreads();
    }

    // Epilogue: write RAW h (scaling deferred to k_scale).
    int g = lane >> 2, t = lane & 3;
#pragma unroll
    for (int rh = 0; rh < 2; rh++) {
        int row = row0g + w * 16 + g + rh * 8;
        if (row < NN) {
#pragma unroll
            for (int nt = 0; nt < 4; nt++) {
                int col = nt * 8 + 2 * t;
                *(float2*)&g_agg[(size_t)row * NC + col] =
                    make_float2(c[nt][rh * 2 + 0], c[nt][rh * 2 + 1]);
            }
        }
    }
}

// ---------------------------------------------------------------- scale (5)
// hs = h * dinv; write f32 seed (in place) + fp16 payload.
__global__ void k_scale() {
    int idx = blockIdx.x * blockDim.x + threadIdx.x;   // float4 id, 8 per node
    if (idx < NN * 8) {
        int node = idx >> 3;
        float di = rsqrtf((float)g_cur[node] + 1.0f);
        float4 h = ((float4*)g_agg)[idx];
        h.x *= di; h.y *= di; h.z *= di; h.w *= di;
        ((float4*)g_agg)[idx] = h;
        half2 p0 = __floats2half2_rn(h.x, h.y);
        half2 p1 = __floats2half2_rn(h.z, h.w);
        ((uint2*)g_hs_h)[idx] = make_uint2(*(unsigned*)&p0, *(unsigned*)&p1);
    }
}

// ---------------------------------------------------------------- gather (6)
__global__ void __launch_bounds__(256) k_gather() {
    int node = (blockIdx.x * blockDim.x + threadIdx.x) >> 5;
    if (node >= NN) return;
    int lane = threadIdx.x & 31;
    int g4 = lane >> 2;
    int l4 = lane & 3;

    size_t start = (size_t)node * CAP;
    int cnt = g_cur[node];
    if (cnt > CAP) cnt = CAP;

    const uint4* hs4 = (const uint4*)g_hs_h;
    float a[8];
#pragma unroll
    for (int c = 0; c < 8; c++) a[c] = 0.0f;

    for (int base = 0; base < cnt; base += 32) {
        int m = cnt - base; if (m > 32) m = 32;
        int es = 0;
        if (lane < m) es = g_esrc[start + base + lane];
        int passes = (m + 7) >> 3;
#pragma unroll 4
        for (int p = 0; p < 4; p++) {
            if (p >= passes) break;
            int idx = p * 8 + g4;
            int sj = __shfl_sync(0xffffffffu, es, idx);
            if (idx < m) {
                uint4 hv = hs4[(size_t)sj * 4 + l4];
                float2 f0 = __half22float2(*(half2*)&hv.x);
                float2 f1 = __half22float2(*(half2*)&hv.y);
                float2 f2 = __half22float2(*(half2*)&hv.z);
                float2 f3 = __half22float2(*(half2*)&hv.w);
                a[0] += f0.x; a[1] += f0.y; a[2] += f1.x; a[3] += f1.y;
                a[4] += f2.x; a[5] += f2.y; a[6] += f3.x; a[7] += f3.y;
            }
        }
    }

#pragma unroll
    for (int c = 0; c < 8; c++) {
        a[c] += __shfl_down_sync(0xffffffffu, a[c], 16);
        a[c] += __shfl_down_sync(0xffffffffu, a[c], 8);
        a[c] += __shfl_down_sync(0xffffffffu, a[c], 4);
    }

    if (lane < 4) {
        float4* p0 = (float4*)&g_agg[(size_t)node * NC + 8 * lane];
        float4 s0 = p0[0], s1 = p0[1];
        p0[0] = make_float4(s0.x + a[0], s0.y + a[1], s0.z + a[2], s0.w + a[3]);
        p0[1] = make_float4(s1.x + a[4], s1.y + a[5], s1.z + a[6], s1.w + a[7]);
    }
}

// ---------------------------------------------------------------- fixup (7)
__global__ void k_fix() {
    int n = g_ovfn;
    if (n > OVFCAP) n = OVFCAP;
    int lane = threadIdx.x & 31;
    int g  = lane >> 3;
    int l8 = lane & 7;
    const uint2* hs2 = (const uint2*)g_hs_h;
    int wid = (blockIdx.x * blockDim.x + threadIdx.x) >> 5;
    int nw  = (gridDim.x * blockDim.x) >> 5;
    for (int j = wid * 4 + g; j < n; j += nw * 4) {
        int2 e = g_ovf[j];
        uint2 hv = hs2[(size_t)e.x * 8 + l8];
        float2 fa = __half22float2(*(half2*)&hv.x);
        float2 fb = __half22float2(*(half2*)&hv.y);
        float* p = &g_agg[(size_t)e.y * NC + l8 * 4];
        asm volatile("red.global.add.v4.f32 [%0], {%1, %2, %3, %4};"
                     :: "l"(p), "f"(fa.x), "f"(fa.y), "f"(fb.x), "f"(fb.y)
                     : "memory");
    }
}

// ---------------------------------------------------------------- pooling (8)
__global__ void __launch_bounds__(256) k_pool(const int* __restrict__ batch) {
    __shared__ float sp[NG * NC];
    __shared__ float sc[NG];
    __shared__ int gmin, gmax;
    int tid = threadIdx.x;
    for (int i = tid; i < NG * NC; i += 256) sp[i] = 0.0f;
    if (tid < NG) sc[tid] = 0.0f;
    if (tid == 0) { gmin = NG; gmax = -1; }
    __syncthreads();

    int warp = tid >> 5, lane = tid & 31;
    int wid = blockIdx.x * 8 + warp;
    int nwarps = PBLK * 8;
    int per = (NN + nwarps - 1) / nwarps;
    int s0 = wid * per;
    int s1 = min(NN, s0 + per);

    float acc = 0.0f, cacc = 0.0f;
    int curg = -1, firstg = NG, lastg = -1;

    for (int i = s0; i < s1; i += 4) {
        int m = s1 - i; if (m > 4) m = 4;
        int   bb[4];
        float vv[4];
        float dd[4];
#pragma unroll
        for (int k = 0; k < 4; k++) {
            if (k < m) {
                bb[k] = __ldg(&batch[i + k]);
                vv[k] = g_agg[(size_t)(i + k) * NC + lane];
                dd[k] = (float)g_cur[i + k];
            }
        }
#pragma unroll
        for (int k = 0; k < 4; k++) {
            if (k < m) {
                if (bb[k] != curg) {
                    if (curg >= 0) {
                        atomicAdd(&sp[curg * NC + lane], acc);
                        if (lane == 0) atomicAdd(&sc[curg], cacc);
                    }
                    curg = bb[k]; acc = 0.0f; cacc = 0.0f;
                    if (curg < firstg) firstg = curg;
                    if (curg > lastg)  lastg = curg;
                }
                acc  += vv[k] * rsqrtf(dd[k] + 1.0f);
                cacc += 1.0f;
            }
        }
    }
    if (curg >= 0) {
        atomicAdd(&sp[curg * NC + lane], acc);
        if (lane == 0) atomicAdd(&sc[curg], cacc);
    }
    if (lane == 0 && lastg >= 0) {
        atomicMin(&gmin, firstg);
        atomicMax(&gmax, lastg);
    }
    __syncthreads();

    int lo = gmin, hi = gmax;
    if (hi >= lo) {
        for (int i = lo * NC + tid; i < (hi + 1) * NC; i += 256)
            atomicAdd(&g_pool[i], sp[i]);
        for (int g = lo + tid; g <= hi; g += 256)
            atomicAdd(&g_cnt[g], sc[g]);
    }
}

// ---------------------------------------------------------------- finalize (9)
__global__ void k_final(const float* __restrict__ b, float* __restrict__ out) {
    int i = blockIdx.x * blockDim.x + threadIdx.x;
    if (i < NG * NC) {
        int g = i >> 5, c = i & 31;
        float cnt = g_cnt[g];
        out[i] = (cnt > 0.0f) ? (g_pool[i] / cnt + b[c]) : 0.0f;
    }
}

// ---------------------------------------------------------------- launch
extern "C" void kernel_launch(void* const* d_in, const int* in_sizes, int n_in,
                              void* d_out, int out_size) {
    const float* x     = (const float*)d_in[0];
    const float* W     = (const float*)d_in[1];
    const float* b     = (const float*)d_in[2];
    const int*   ei    = (const int*)d_in[3];
    const int*   batch = (const int*)d_in[4];
    float*       out   = (float*)d_out;

    const int* src = ei;        // edge_index[0]
    const int* dst = ei + NE;   // edge_index[1]

    k_zero <<<(NN + 255) / 256, 256>>>();
    k_prep <<<32, 256>>>(W);
    k_pad  <<<1, 32>>>();
    k_fused<<<NGEMM * 5, 256>>>(src, dst, x);              // slot 4 -> ncu
    k_scale<<<(NN * 8 + 255) / 256, 256>>>();
    k_gather<<<(NN + 7) / 8, 256>>>();
    k_fix  <<<16, 256>>>();
    k_pool <<<PBLK, 256>>>(batch);
    k_final<<<(NG * NC + 255) / 256, 256>>>(b, out);
}

// round 16
// speedup vs baseline: 1.9341x; 1.0381x over previous
#include <cuda_runtime.h>
#include <cuda_fp16.h>

#define NN 100000
#define NE 3200000
#define DIMK 256
#define NC 32
#define NG 64
#define CAP 96     // fixed CSR stride, multiple of 8 (deg ~ Poisson(32))
#define OVFCAP 8192
#define PBLK 256   // pool blocks
#define GR 128     // rows per gemm block
#define RS 36      // stage row stride (floats): 144B, ldsm conflict-free
#define NGEMM ((NN + GR - 1) / GR)      // 782 gemm-role blocks
#define NBUILD ((NE / 4 + 255) / 256)   // 3125 build-role blocks

// Scratch (device globals; no allocation allowed)
__device__ int    g_cur[NN];                      // build cursor == final in-degree
__device__ int    g_esrc[(size_t)NN * CAP];       // fixed-stride CSR src lists
__device__ int2   g_ovf[OVFCAP];
__device__ int    g_ovfn;
__device__ __half g_hs_h[(size_t)(NN + 1) * NC];  // +1 dummy zero row (padding target)
__device__ float  g_agg[(size_t)NN * NC];         // raw h -> hs seed + edge sums
__device__ float  g_pool[NG * NC];
__device__ float  g_cnt[NG];
__device__ float4 g_wf4[4096];                    // W frags: [hi|lo][kstep][ntp][lane]

__device__ __forceinline__ unsigned tf32_bits(float v) {
    unsigned r;
    asm("cvt.rna.tf32.f32 %0, %1;" : "=r"(r) : "f"(v));
    return r;
}
__device__ __forceinline__ float to_tf32(float v) {
    return __uint_as_float(tf32_bits(v));
}
__device__ __forceinline__ void ldsm4(unsigned a[4], unsigned addr) {
    asm volatile("ldmatrix.sync.aligned.m8n8.x4.shared.b16 {%0,%1,%2,%3}, [%4];"
                 : "=r"(a[0]), "=r"(a[1]), "=r"(a[2]), "=r"(a[3]) : "r"(addr));
}
__device__ __forceinline__ void mma8(float c[4], const unsigned a[4],
                                     unsigned b0, unsigned b1) {
    asm volatile("mma.sync.aligned.m16n8k8.row.col.f32.tf32.tf32.f32 "
                 "{%0,%1,%2,%3}, {%4,%5,%6,%7}, {%8,%9}, {%0,%1,%2,%3};"
                 : "+f"(c[0]), "+f"(c[1]), "+f"(c[2]), "+f"(c[3])
                 : "r"(a[0]), "r"(a[1]), "r"(a[2]), "r"(a[3]), "r"(b0), "r"(b1));
}
__device__ __forceinline__ void cpasync16(unsigned dst, const void* src) {
    asm volatile("cp.async.cg.shared.global [%0], [%1], 16;"
                 :: "r"(dst), "l"(src) : "memory");
}

// ---------------------------------------------------------------- init (1)
// Zero cursors/pool/ovfn AND compute W fragments once.
__global__ void k_init(const float* __restrict__ W) {
    int i = blockIdx.x * blockDim.x + threadIdx.x;
    if (i < NN) g_cur[i] = 0;
    if (i < NG * NC) g_pool[i] = 0.0f;
    if (i < NG) g_cnt[i] = 0.0f;
    if (i == 0) g_ovfn = 0;
    if (i < 8192) {
        int kstep = i >> 8;
        int rem   = i & 255;
        int ntp   = rem >> 7;
        int rem2  = rem & 127;
        int ln    = rem2 >> 2;
        int j     = rem2 & 3;
        int nt = ntp * 2 + (j >> 1);
        int b  = j & 1;
        int k  = kstep * 8 + (ln & 3) + b * 4;
        int n  = nt * 8 + (ln >> 2);
        float v  = W[k * NC + n];
        float hi = to_tf32(v);
        float lo = to_tf32(v - hi);
        int slot = (kstep * 2 + ntp) * 32 + ln;
        ((float*)&g_wf4[slot])[j]        = hi;
        ((float*)&g_wf4[2048 + slot])[j] = lo;
    }
}

// ---------------------------------------------------------------- fused (2)
// Role-split: bid%5==0 -> tf32 MMA gemm (raw h); else -> CSR build.
__global__ void __launch_bounds__(256) k_fused(const int* __restrict__ src,
                                               const int* __restrict__ dst,
                                               const float* __restrict__ x) {
    __shared__ float st[2 * GR * RS];   // gemm role only

    int bid = blockIdx.x;
    int tid = threadIdx.x;

    if (bid % 5 != 0) {
        // ---- build role ----
        int build_id = bid - bid / 5 - 1;
        if (build_id >= NBUILD) return;
        int i = build_id * 256 + tid;
        if (i * 4 < NE) {
            int4 s = ((const int4*)src)[i];
            int4 d = ((const int4*)dst)[i];
#pragma unroll
            for (int k = 0; k < 4; k++) {
                int dd = (k == 0) ? d.x : (k == 1) ? d.y : (k == 2) ? d.z : d.w;
                int ss = (k == 0) ? s.x : (k == 1) ? s.y : (k == 2) ? s.z : s.w;
                int p = atomicAdd(&g_cur[dd], 1);
                if (p < CAP) {
                    g_esrc[(size_t)dd * CAP + p] = ss;
                } else {
                    int q = atomicAdd(&g_ovfn, 1);
                    if (q < OVFCAP) g_ovf[q] = make_int2(ss, dd);
                }
            }
        }
        return;
    }

    // ---- gemm role ----
    int gb = bid / 5;
    int w = tid >> 5, lane = tid & 31;
    int row0g = gb * GR;
    unsigned stbase = (unsigned)__cvta_generic_to_shared(st);

    auto stage = [&](int cc, int bsel) {
#pragma unroll
        for (int i = 0; i < 4; i++) {
            int f = tid + i * 256;
            int row = f >> 3, q = f & 7;
            int rr = row0g + row; if (rr >= NN) rr = NN - 1;
            const float* srcp = x + (size_t)rr * DIMK + cc * 32 + q * 4;
            unsigned dstp = stbase + (unsigned)((bsel * GR * RS + row * RS + q * 4) * 4);
            cpasync16(dstp, srcp);
        }
        asm volatile("cp.async.commit_group;" ::: "memory");
    };

    float c[4][4];
#pragma unroll
    for (int nt = 0; nt < 4; nt++)
#pragma unroll
        for (int q = 0; q < 4; q++) c[nt][q] = 0.0f;

    stage(0, 0);

    for (int cc = 0; cc < 8; cc++) {
        if (cc < 7) stage(cc + 1, (cc + 1) & 1);
        if (cc < 7) asm volatile("cp.async.wait_group 1;" ::: "memory");
        else        asm volatile("cp.async.wait_group 0;" ::: "memory");
        __syncthreads();

        const float* buf = st + (cc & 1) * GR * RS;
#pragma unroll
        for (int ks = 0; ks < 4; ks++) {
            int kstep = cc * 4 + ks;
            int soff = (w * 16 + (lane & 15)) * RS + ks * 8 + (lane >> 4) * 4;
            unsigned araw[4];
            ldsm4(araw, (unsigned)__cvta_generic_to_shared(buf + soff));
            unsigned ah[4], al[4];
#pragma unroll
            for (int i = 0; i < 4; i++) {
                float v = __uint_as_float(araw[i]);
                float h = to_tf32(v);
                ah[i] = __float_as_uint(h);
                al[i] = tf32_bits(v - h);
            }
#pragma unroll
            for (int ntp = 0; ntp < 2; ntp++) {
                int slot = (kstep * 2 + ntp) * 32 + lane;
                float4 whf = __ldg(&g_wf4[slot]);
                float4 wlf = __ldg(&g_wf4[2048 + slot]);
                uint4 wh = *(uint4*)&whf;
                uint4 wl = *(uint4*)&wlf;
                mma8(c[2 * ntp],     ah, wh.x, wh.y);
                mma8(c[2 * ntp],     ah, wl.x, wl.y);
                mma8(c[2 * ntp],     al, wh.x, wh.y);
                mma8(c[2 * ntp + 1], ah, wh.z, wh.w);
                mma8(c[2 * ntp + 1], ah, wl.z, wl.w);
                mma8(c[2 * ntp + 1], al, wh.z, wh.w);
            }
        }
        __syncthreads();
    }

    int g = lane >> 2, t = lane & 3;
#pragma unroll
    for (int rh = 0; rh < 2; rh++) {
        int row = row0g + w * 16 + g + rh * 8;
        if (row < NN) {
#pragma unroll
            for (int nt = 0; nt < 4; nt++) {
                int col = nt * 8 + 2 * t;
                *(float2*)&g_agg[(size_t)row * NC + col] =
                    make_float2(c[nt][rh * 2 + 0], c[nt][rh * 2 + 1]);
            }
        }
    }
}

// ---------------------------------------------------------------- scale (3)
// hs = h*dinv (f32 seed in place + fp16 payload); pad CSR lists to mult-of-8
// with dummy node NN; zero the dummy payload row.
__global__ void k_scale() {
    int idx = blockIdx.x * blockDim.x + threadIdx.x;   // float4 id, 8 per node
    if (idx < NN * 8) {
        int node = idx >> 3;
        int cnt = g_cur[node];
        float di = rsqrtf((float)cnt + 1.0f);
        float4 h = ((float4*)g_agg)[idx];
        h.x *= di; h.y *= di; h.z *= di; h.w *= di;
        ((float4*)g_agg)[idx] = h;
        half2 p0 = __floats2half2_rn(h.x, h.y);
        half2 p1 = __floats2half2_rn(h.z, h.w);
        ((uint2*)g_hs_h)[idx] = make_uint2(*(unsigned*)&p0, *(unsigned*)&p1);
        if ((idx & 7) == 0) {
            int cc = min(cnt, CAP);
            int c8 = (cc + 7) & ~7;            // <= CAP since CAP % 8 == 0
            for (int j = cc; j < c8; j++) g_esrc[(size_t)node * CAP + j] = NN;
        }
    } else if (idx < NN * 8 + 8) {
        ((uint2*)g_hs_h)[(size_t)NN * 8 + (idx - NN * 8)] = make_uint2(0u, 0u);
    }
}

// ---------------------------------------------------------------- gather (4, ncu)
// Warp per node; 8 lanes/edge (uint2 payload), UNCONDITIONAL inner loop via
// dummy-padded lists; 2-level shuffle reduce; float4 store.
__global__ void __launch_bounds__(256) k_gather() {
    int node = (blockIdx.x * blockDim.x + threadIdx.x) >> 5;
    if (node >= NN) return;
    int lane = threadIdx.x & 31;
    int g8 = lane >> 3;   // edge subgroup 0..3
    int l8 = lane & 7;    // channel quad (4 ch = 8B)

    size_t start = (size_t)node * CAP;
    int cnt = min(g_cur[node], CAP);
    int cnt8 = (cnt + 7) & ~7;            // padded length (mult of 8, <= CAP)

    const uint2* hs2 = (const uint2*)g_hs_h;
    float a0 = 0.0f, a1 = 0.0f, a2 = 0.0f, a3 = 0.0f;

    for (int base = 0; base < cnt8; base += 32) {
        int es = g_esrc[start + base + lane];     // coalesced; extras unused
        int npass = min(8, (cnt8 - base) >> 2);   // passes of 4 edges
#pragma unroll 8
        for (int p = 0; p < npass; p++) {
            int sj = __shfl_sync(0xffffffffu, es, p * 4 + g8);
            uint2 hv = hs2[(size_t)sj * 8 + l8];  // no guard: dummy row is zero
            float2 f0 = __half22float2(*(half2*)&hv.x);
            float2 f1 = __half22float2(*(half2*)&hv.y);
            a0 += f0.x; a1 += f0.y; a2 += f1.x; a3 += f1.y;
        }
    }

    // combine 4 edge-subgroups (same l8): distances 16, 8
    a0 += __shfl_down_sync(0xffffffffu, a0, 16);
    a1 += __shfl_down_sync(0xffffffffu, a1, 16);
    a2 += __shfl_down_sync(0xffffffffu, a2, 16);
    a3 += __shfl_down_sync(0xffffffffu, a3, 16);
    a0 += __shfl_down_sync(0xffffffffu, a0, 8);
    a1 += __shfl_down_sync(0xffffffffu, a1, 8);
    a2 += __shfl_down_sync(0xffffffffu, a2, 8);
    a3 += __shfl_down_sync(0xffffffffu, a3, 8);

    if (lane < 8) {   // lane owns channels [4*lane, 4*lane+4)
        float4* p = (float4*)&g_agg[(size_t)node * NC + 4 * lane];
        float4 s = *p;                      // gemm self-loop seed (scaled)
        *p = make_float4(s.x + a0, s.y + a1, s.z + a2, s.w + a3);
    }
}

// ---------------------------------------------------------------- fixup (5)
__global__ void k_fix() {
    int n = g_ovfn;
    if (n > OVFCAP) n = OVFCAP;
    int lane = threadIdx.x & 31;
    int g  = lane >> 3;
    int l8 = lane & 7;
    const uint2* hs2 = (const uint2*)g_hs_h;
    int wid = (blockIdx.x * blockDim.x + threadIdx.x) >> 5;
    int nw  = (gridDim.x * blockDim.x) >> 5;
    for (int j = wid * 4 + g; j < n; j += nw * 4) {
        int2 e = g_ovf[j];
        uint2 hv = hs2[(size_t)e.x * 8 + l8];
        float2 fa = __half22float2(*(half2*)&hv.x);
        float2 fb = __half22float2(*(half2*)&hv.y);
        float* p = &g_agg[(size_t)e.y * NC + l8 * 4];
        asm volatile("red.global.add.v4.f32 [%0], {%1, %2, %3, %4};"
                     :: "l"(p), "f"(fa.x), "f"(fa.y), "f"(fb.x), "f"(fb.y)
                     : "memory");
    }
}

// ---------------------------------------------------------------- pooling (6)
__global__ void __launch_bounds__(256) k_pool(const int* __restrict__ batch) {
    __shared__ float sp[NG * NC];
    __shared__ float sc[NG];
    __shared__ int gmin, gmax;
    int tid = threadIdx.x;
    for (int i = tid; i < NG * NC; i += 256) sp[i] = 0.0f;
    if (tid < NG) sc[tid] = 0.0f;
    if (tid == 0) { gmin = NG; gmax = -1; }
    __syncthreads();

    int warp = tid >> 5, lane = tid & 31;
    int wid = blockIdx.x * 8 + warp;
    int nwarps = PBLK * 8;
    int per = (NN + nwarps - 1) / nwarps;
    int s0 = wid * per;
    int s1 = min(NN, s0 + per);

    float acc = 0.0f, cacc = 0.0f;
    int curg = -1, firstg = NG, lastg = -1;

    for (int i = s0; i < s1; i += 4) {
        int m = s1 - i; if (m > 4) m = 4;
        int   bb[4];
        float vv[4];
        float dd[4];
#pragma unroll
        for (int k = 0; k < 4; k++) {
            if (k < m) {
                bb[k] = __ldg(&batch[i + k]);
                vv[k] = g_agg[(size_t)(i + k) * NC + lane];
                dd[k] = (float)g_cur[i + k];
            }
        }
#pragma unroll
        for (int k = 0; k < 4; k++) {
            if (k < m) {
                if (bb[k] != curg) {
                    if (curg >= 0) {
                        atomicAdd(&sp[curg * NC + lane], acc);
                        if (lane == 0) atomicAdd(&sc[curg], cacc);
                    }
                    curg = bb[k]; acc = 0.0f; cacc = 0.0f;
                    if (curg < firstg) firstg = curg;
                    if (curg > lastg)  lastg = curg;
                }
                acc  += vv[k] * rsqrtf(dd[k] + 1.0f);
                cacc += 1.0f;
            }
        }
    }
    if (curg >= 0) {
        atomicAdd(&sp[curg * NC + lane], acc);
        if (lane == 0) atomicAdd(&sc[curg], cacc);
    }
    if (lane == 0 && lastg >= 0) {
        atomicMin(&gmin, firstg);
        atomicMax(&gmax, lastg);
    }
    __syncthreads();

    int lo = gmin, hi = gmax;
    if (hi >= lo) {
        for (int i = lo * NC + tid; i < (hi + 1) * NC; i += 256)
            atomicAdd(&g_pool[i], sp[i]);
        for (int g = lo + tid; g <= hi; g += 256)
            atomicAdd(&g_cnt[g], sc[g]);
    }
}

// ---------------------------------------------------------------- finalize (7)
__global__ void k_final(const float* __restrict__ b, float* __restrict__ out) {
    int i = blockIdx.x * blockDim.x + threadIdx.x;
    if (i < NG * NC) {
        int g = i >> 5, c = i & 31;
        float cnt = g_cnt[g];
        out[i] = (cnt > 0.0f) ? (g_pool[i] / cnt + b[c]) : 0.0f;
    }
}

// ---------------------------------------------------------------- launch
extern "C" void kernel_launch(void* const* d_in, const int* in_sizes, int n_in,
                              void* d_out, int out_size) {
    const float* x     = (const float*)d_in[0];
    const float* W     = (const float*)d_in[1];
    const float* b     = (const float*)d_in[2];
    const int*   ei    = (const int*)d_in[3];
    const int*   batch = (const int*)d_in[4];
    float*       out   = (float*)d_out;

    const int* src = ei;        // edge_index[0]
    const int* dst = ei + NE;   // edge_index[1]

    k_init <<<(NN + 255) / 256, 256>>>(W);
    k_fused<<<NGEMM * 5, 256>>>(src, dst, x);
    k_scale<<<(NN * 8 + 8 + 255) / 256, 256>>>();
    k_gather<<<(NN + 7) / 8, 256>>>();                     // slot 4 -> ncu
    k_fix  <<<16, 256>>>();
    k_pool <<<PBLK, 256>>>(batch);
    k_final<<<(NG * NC + 255) / 256, 256>>>(b, out);
}

// round 17
// speedup vs baseline: 1.9458x; 1.0060x over previous
#include <cuda_runtime.h>
#include <cuda_fp16.h>

#define NN 100000
#define NE 3200000
#define DIMK 256
#define NC 32
#define NG 64
#define CAP 96     // fixed CSR stride, multiple of 8 (deg ~ Poisson(32))
#define OVFCAP 8192
#define PBLK 256   // pool blocks
#define GR 128     // rows per gemm block
#define RS 36      // stage row stride (floats): 144B, ldsm conflict-free
#define NGEMM ((NN + GR - 1) / GR)        // 782 gemm-role blocks
#define NBUILD2 ((NE / 8 + 255) / 256)    // 1563 build-role blocks (8 edges/thread)

// Scratch (device globals; no allocation allowed)
__device__ int    g_cur[NN];                      // build cursor == final in-degree
__device__ int    g_esrc[(size_t)NN * CAP];       // fixed-stride CSR src lists
__device__ int2   g_ovf[OVFCAP];
__device__ int    g_ovfn;
__device__ __half g_hs_h[(size_t)(NN + 1) * NC];  // +1 dummy zero row (padding target)
__device__ float  g_agg[(size_t)NN * NC];         // RAW h -> gather folds dinv
__device__ float  g_pool[NG * NC];
__device__ float  g_cnt[NG];
__device__ float4 g_wf4[4096];                    // W frags: [hi|lo][kstep][ntp][lane]

__device__ __forceinline__ unsigned tf32_bits(float v) {
    unsigned r;
    asm("cvt.rna.tf32.f32 %0, %1;" : "=r"(r) : "f"(v));
    return r;
}
__device__ __forceinline__ float to_tf32(float v) {
    return __uint_as_float(tf32_bits(v));
}
__device__ __forceinline__ void ldsm4(unsigned a[4], unsigned addr) {
    asm volatile("ldmatrix.sync.aligned.m8n8.x4.shared.b16 {%0,%1,%2,%3}, [%4];"
                 : "=r"(a[0]), "=r"(a[1]), "=r"(a[2]), "=r"(a[3]) : "r"(addr));
}
__device__ __forceinline__ void mma8(float c[4], const unsigned a[4],
                                     unsigned b0, unsigned b1) {
    asm volatile("mma.sync.aligned.m16n8k8.row.col.f32.tf32.tf32.f32 "
                 "{%0,%1,%2,%3}, {%4,%5,%6,%7}, {%8,%9}, {%0,%1,%2,%3};"
                 : "+f"(c[0]), "+f"(c[1]), "+f"(c[2]), "+f"(c[3])
                 : "r"(a[0]), "r"(a[1]), "r"(a[2]), "r"(a[3]), "r"(b0), "r"(b1));
}
__device__ __forceinline__ void cpasync16(unsigned dst, const void* src) {
    asm volatile("cp.async.cg.shared.global [%0], [%1], 16;"
                 :: "r"(dst), "l"(src) : "memory");
}

// ---------------------------------------------------------------- init (1)
__global__ void k_init(const float* __restrict__ W) {
    int i = blockIdx.x * blockDim.x + threadIdx.x;
    if (i < NN) g_cur[i] = 0;
    if (i < NG * NC) g_pool[i] = 0.0f;
    if (i < NG) g_cnt[i] = 0.0f;
    if (i == 0) g_ovfn = 0;
    if (i < 8192) {
        int kstep = i >> 8;
        int rem   = i & 255;
        int ntp   = rem >> 7;
        int rem2  = rem & 127;
        int ln    = rem2 >> 2;
        int j     = rem2 & 3;
        int nt = ntp * 2 + (j >> 1);
        int b  = j & 1;
        int k  = kstep * 8 + (ln & 3) + b * 4;
        int n  = nt * 8 + (ln >> 2);
        float v  = W[k * NC + n];
        float hi = to_tf32(v);
        float lo = to_tf32(v - hi);
        int slot = (kstep * 2 + ntp) * 32 + ln;
        ((float*)&g_wf4[slot])[j]        = hi;
        ((float*)&g_wf4[2048 + slot])[j] = lo;
    }
}

// ---------------------------------------------------------------- pads (2,3)
__global__ void k_pad1() { if (blockIdx.x == 0 && threadIdx.x == 0) g_ovfn = 0; }
__global__ void k_pad2() { }

// ---------------------------------------------------------------- fused (4, ncu)
// bid%3==0 -> tf32 MMA gemm (raw h); else -> CSR build (8 edges/thread, ILP).
__global__ void __launch_bounds__(256) k_fused(const int* __restrict__ src,
                                               const int* __restrict__ dst,
                                               const float* __restrict__ x) {
    __shared__ float st[2 * GR * RS];   // gemm role only

    int bid = blockIdx.x;
    int tid = threadIdx.x;

    if (bid % 3 != 0) {
        // ---- build role: 8 edges per thread (2x int4), high MLP ----
        int build_id = bid - bid / 3 - 1;
        if (build_id >= NBUILD2) return;
        int base = build_id * 256 + tid;      // 0..400K-1, covers 2 int4 each
#pragma unroll
        for (int h = 0; h < 2; h++) {
            int i = base * 2 + h;
            if (i * 4 < NE) {
                int4 s = ((const int4*)src)[i];
                int4 d = ((const int4*)dst)[i];
#pragma unroll
                for (int k = 0; k < 4; k++) {
                    int dd = (k == 0) ? d.x : (k == 1) ? d.y : (k == 2) ? d.z : d.w;
                    int ss = (k == 0) ? s.x : (k == 1) ? s.y : (k == 2) ? s.z : s.w;
                    int p = atomicAdd(&g_cur[dd], 1);
                    if (p < CAP) {
                        g_esrc[(size_t)dd * CAP + p] = ss;
                    } else {
                        int q = atomicAdd(&g_ovfn, 1);
                        if (q < OVFCAP) g_ovf[q] = make_int2(ss, dd);
                    }
                }
            }
        }
        return;
    }

    // ---- gemm role ----
    int gb = bid / 3;
    int w = tid >> 5, lane = tid & 31;
    int row0g = gb * GR;
    unsigned stbase = (unsigned)__cvta_generic_to_shared(st);

    auto stage = [&](int cc, int bsel) {
#pragma unroll
        for (int i = 0; i < 4; i++) {
            int f = tid + i * 256;
            int row = f >> 3, q = f & 7;
            int rr = row0g + row; if (rr >= NN) rr = NN - 1;
            const float* srcp = x + (size_t)rr * DIMK + cc * 32 + q * 4;
            unsigned dstp = stbase + (unsigned)((bsel * GR * RS + row * RS + q * 4) * 4);
            cpasync16(dstp, srcp);
        }
        asm volatile("cp.async.commit_group;" ::: "memory");
    };

    float c[4][4];
#pragma unroll
    for (int nt = 0; nt < 4; nt++)
#pragma unroll
        for (int q = 0; q < 4; q++) c[nt][q] = 0.0f;

    stage(0, 0);

    for (int cc = 0; cc < 8; cc++) {
        if (cc < 7) stage(cc + 1, (cc + 1) & 1);
        if (cc < 7) asm volatile("cp.async.wait_group 1;" ::: "memory");
        else        asm volatile("cp.async.wait_group 0;" ::: "memory");
        __syncthreads();

        const float* buf = st + (cc & 1) * GR * RS;
#pragma unroll
        for (int ks = 0; ks < 4; ks++) {
            int kstep = cc * 4 + ks;
            int soff = (w * 16 + (lane & 15)) * RS + ks * 8 + (lane >> 4) * 4;
            unsigned araw[4];
            ldsm4(araw, (unsigned)__cvta_generic_to_shared(buf + soff));
            unsigned ah[4], al[4];
#pragma unroll
            for (int i = 0; i < 4; i++) {
                float v = __uint_as_float(araw[i]);
                float h = to_tf32(v);
                ah[i] = __float_as_uint(h);
                al[i] = tf32_bits(v - h);
            }
#pragma unroll
            for (int ntp = 0; ntp < 2; ntp++) {
                int slot = (kstep * 2 + ntp) * 32 + lane;
                float4 whf = __ldg(&g_wf4[slot]);
                float4 wlf = __ldg(&g_wf4[2048 + slot]);
                uint4 wh = *(uint4*)&whf;
                uint4 wl = *(uint4*)&wlf;
                mma8(c[2 * ntp],     ah, wh.x, wh.y);
                mma8(c[2 * ntp],     ah, wl.x, wl.y);
                mma8(c[2 * ntp],     al, wh.x, wh.y);
                mma8(c[2 * ntp + 1], ah, wh.z, wh.w);
                mma8(c[2 * ntp + 1], ah, wl.z, wl.w);
                mma8(c[2 * ntp + 1], al, wh.z, wh.w);
            }
        }
        __syncthreads();
    }

    int g = lane >> 2, t = lane & 3;
#pragma unroll
    for (int rh = 0; rh < 2; rh++) {
        int row = row0g + w * 16 + g + rh * 8;
        if (row < NN) {
#pragma unroll
            for (int nt = 0; nt < 4; nt++) {
                int col = nt * 8 + 2 * t;
                *(float2*)&g_agg[(size_t)row * NC + col] =
                    make_float2(c[nt][rh * 2 + 0], c[nt][rh * 2 + 1]);
            }
        }
    }
}

// ---------------------------------------------------------------- scale (5)
// fp16 payload hs = h*dinv (g_agg stays RAW); pad CSR lists; zero dummy row.
__global__ void k_scale() {
    int idx = blockIdx.x * blockDim.x + threadIdx.x;   // float4 id, 8 per node
    if (idx < NN * 8) {
        int node = idx >> 3;
        int cnt = g_cur[node];
        float di = rsqrtf((float)cnt + 1.0f);
        float4 h = ((float4*)g_agg)[idx];
        half2 p0 = __floats2half2_rn(h.x * di, h.y * di);
        half2 p1 = __floats2half2_rn(h.z * di, h.w * di);
        ((uint2*)g_hs_h)[idx] = make_uint2(*(unsigned*)&p0, *(unsigned*)&p1);
        if ((idx & 7) == 0) {
            int cc = min(cnt, CAP);
            int c8 = (cc + 7) & ~7;            // <= CAP since CAP % 8 == 0
            for (int j = cc; j < c8; j++) g_esrc[(size_t)node * CAP + j] = NN;
        }
    } else if (idx < NN * 8 + 8) {
        ((uint2*)g_hs_h)[(size_t)NN * 8 + (idx - NN * 8)] = make_uint2(0u, 0u);
    }
}

// ---------------------------------------------------------------- gather (6)
// Warp per node; unconditional inner loop; seed = raw h scaled by dinv here.
__global__ void __launch_bounds__(256) k_gather() {
    int node = (blockIdx.x * blockDim.x + threadIdx.x) >> 5;
    if (node >= NN) return;
    int lane = threadIdx.x & 31;
    int g8 = lane >> 3;   // edge subgroup 0..3
    int l8 = lane & 7;    // channel quad (4 ch = 8B)

    size_t start = (size_t)node * CAP;
    int deg = g_cur[node];
    float di = rsqrtf((float)deg + 1.0f);
    int cnt = min(deg, CAP);
    int cnt8 = (cnt + 7) & ~7;

    const uint2* hs2 = (const uint2*)g_hs_h;
    float a0 = 0.0f, a1 = 0.0f, a2 = 0.0f, a3 = 0.0f;

    for (int base = 0; base < cnt8; base += 32) {
        int es = g_esrc[start + base + lane];
        int npass = min(8, (cnt8 - base) >> 2);
#pragma unroll 8
        for (int p = 0; p < npass; p++) {
            int sj = __shfl_sync(0xffffffffu, es, p * 4 + g8);
            uint2 hv = hs2[(size_t)sj * 8 + l8];
            float2 f0 = __half22float2(*(half2*)&hv.x);
            float2 f1 = __half22float2(*(half2*)&hv.y);
            a0 += f0.x; a1 += f0.y; a2 += f1.x; a3 += f1.y;
        }
    }

    a0 += __shfl_down_sync(0xffffffffu, a0, 16);
    a1 += __shfl_down_sync(0xffffffffu, a1, 16);
    a2 += __shfl_down_sync(0xffffffffu, a2, 16);
    a3 += __shfl_down_sync(0xffffffffu, a3, 16);
    a0 += __shfl_down_sync(0xffffffffu, a0, 8);
    a1 += __shfl_down_sync(0xffffffffu, a1, 8);
    a2 += __shfl_down_sync(0xffffffffu, a2, 8);
    a3 += __shfl_down_sync(0xffffffffu, a3, 8);

    if (lane < 8) {   // seed is RAW h -> fold dinv here (hs_self = h*di)
        float4* p = (float4*)&g_agg[(size_t)node * NC + 4 * lane];
        float4 s = *p;
        *p = make_float4(fmaf(s.x, di, a0), fmaf(s.y, di, a1),
                         fmaf(s.z, di, a2), fmaf(s.w, di, a3));
    }
}

// ---------------------------------------------------------------- fixup (7)
__global__ void k_fix() {
    int n = g_ovfn;
    if (n > OVFCAP) n = OVFCAP;
    int lane = threadIdx.x & 31;
    int g  = lane >> 3;
    int l8 = lane & 7;
    const uint2* hs2 = (const uint2*)g_hs_h;
    int wid = (blockIdx.x * blockDim.x + threadIdx.x) >> 5;
    int nw  = (gridDim.x * blockDim.x) >> 5;
    for (int j = wid * 4 + g; j < n; j += nw * 4) {
        int2 e = g_ovf[j];
        uint2 hv = hs2[(size_t)e.x * 8 + l8];
        float2 fa = __half22float2(*(half2*)&hv.x);
        float2 fb = __half22float2(*(half2*)&hv.y);
        float* p = &g_agg[(size_t)e.y * NC + l8 * 4];
        asm volatile("red.global.add.v4.f32 [%0], {%1, %2, %3, %4};"
                     :: "l"(p), "f"(fa.x), "f"(fa.y), "f"(fb.x), "f"(fb.y)
                     : "memory");
    }
}

// ---------------------------------------------------------------- pooling (8)
__global__ void __launch_bounds__(256) k_pool(const int* __restrict__ batch) {
    __shared__ float sp[NG * NC];
    __shared__ float sc[NG];
    __shared__ int gmin, gmax;
    int tid = threadIdx.x;
    for (int i = tid; i < NG * NC; i += 256) sp[i] = 0.0f;
    if (tid < NG) sc[tid] = 0.0f;
    if (tid == 0) { gmin = NG; gmax = -1; }
    __syncthreads();

    int warp = tid >> 5, lane = tid & 31;
    int wid = blockIdx.x * 8 + warp;
    int nwarps = PBLK * 8;
    int per = (NN + nwarps - 1) / nwarps;
    int s0 = wid * per;
    int s1 = min(NN, s0 + per);

    float acc = 0.0f, cacc = 0.0f;
    int curg = -1, firstg = NG, lastg = -1;

    for (int i = s0; i < s1; i += 4) {
        int m = s1 - i; if (m > 4) m = 4;
        int   bb[4];
        float vv[4];
        float dd[4];
#pragma unroll
        for (int k = 0; k < 4; k++) {
            if (k < m) {
                bb[k] = __ldg(&batch[i + k]);
                vv[k] = g_agg[(size_t)(i + k) * NC + lane];
                dd[k] = (float)g_cur[i + k];
            }
        }
#pragma unroll
        for (int k = 0; k < 4; k++) {
            if (k < m) {
                if (bb[k] != curg) {
                    if (curg >= 0) {
                        atomicAdd(&sp[curg * NC + lane], acc);
                        if (lane == 0) atomicAdd(&sc[curg], cacc);
                    }
                    curg = bb[k]; acc = 0.0f; cacc = 0.0f;
                    if (curg < firstg) firstg = curg;
                    if (curg > lastg)  lastg = curg;
                }
                acc  += vv[k] * rsqrtf(dd[k] + 1.0f);
                cacc += 1.0f;
            }
        }
    }
    if (curg >= 0) {
        atomicAdd(&sp[curg * NC + lane], acc);
        if (lane == 0) atomicAdd(&sc[curg], cacc);
    }
    if (lane == 0 && lastg >= 0) {
        atomicMin(&gmin, firstg);
        atomicMax(&gmax, lastg);
    }
    __syncthreads();

    int lo = gmin, hi = gmax;
    if (hi >= lo) {
        for (int i = lo * NC + tid; i < (hi + 1) * NC; i += 256)
            atomicAdd(&g_pool[i], sp[i]);
        for (int g = lo + tid; g <= hi; g += 256)
            atomicAdd(&g_cnt[g], sc[g]);
    }
}

// ---------------------------------------------------------------- finalize (9)
__global__ void k_final(const float* __restrict__ b, float* __restrict__ out) {
    int i = blockIdx.x * blockDim.x + threadIdx.x;
    if (i < NG * NC) {
        int g = i >> 5, c = i & 31;
        float cnt = g_cnt[g];
        out[i] = (cnt > 0.0f) ? (g_pool[i] / cnt + b[c]) : 0.0f;
    }
}

// ---------------------------------------------------------------- launch
extern "C" void kernel_launch(void* const* d_in, const int* in_sizes, int n_in,
                              void* d_out, int out_size) {
    const float* x     = (const float*)d_in[0];
    const float* W     = (const float*)d_in[1];
    const float* b     = (const float*)d_in[2];
    const int*   ei    = (const int*)d_in[3];
    const int*   batch = (const int*)d_in[4];
    float*       out   = (float*)d_out;

    const int* src = ei;        // edge_index[0]
    const int* dst = ei + NE;   // edge_index[1]

    k_init <<<(NN + 255) / 256, 256>>>(W);
    k_pad1 <<<1, 32>>>();
    k_pad2 <<<1, 32>>>();
    k_fused<<<NGEMM * 3, 256>>>(src, dst, x);              // slot 4 -> ncu
    k_scale<<<(NN * 8 + 8 + 255) / 256, 256>>>();
    k_gather<<<(NN + 7) / 8, 256>>>();
    k_fix  <<<16, 256>>>();
    k_pool <<<PBLK, 256>>>(batch);
    k_final<<<(NG * NC + 255) / 256, 256>>>(b, out);
}